// round 2
// baseline (speedup 1.0000x reference)
#include <cuda_runtime.h>
#include <math.h>

#define BB 512
#define SS 336
#define FF 16
#define HH 256
#define PP 48
#define G3 768   // 3*HH

// ---------------- scratch (device globals; allocation-free) ----------------
__device__ float g_h[2][BB*HH];        // ping-pong hidden state (enc, then dec)
__device__ float g_y[2][BB*FF];        // ping-pong decoder y
__device__ float g_comb[BB*HH];        // attention combine output
__device__ float g_eout[BB*SS*HH];     // encoder outputs (176 MB)
__device__ float g_WhhT[HH*G3];        // enc Whh transposed: [k][j]
__device__ float g_WihT[FF*G3];        // enc Wih transposed
__device__ float g_dWihT[HH*G3];       // dec Wih transposed
__device__ float g_dWhhT[HH*G3];       // dec Whh transposed
__device__ float g_attWT[(HH+FF)*SS];  // att_W transposed: [k][s]

// ---------------- helpers ----------------
__device__ __forceinline__ float sigf(float x) { return 1.f / (1.f + __expf(-x)); }

__global__ void k_transpose(const float* __restrict__ in, float* __restrict__ out,
                            int rows, int cols) {
    int idx = blockIdx.x * 256 + threadIdx.x;
    if (idx < rows * cols) {
        int r = idx / cols, c = idx % cols;
        out[c * rows + r] = in[idx];
    }
}

__global__ void k_init(const float* __restrict__ xb) {
    int idx = blockIdx.x * 256 + threadIdx.x;
    if (idx < BB * HH) g_h[0][idx] = 0.f;
    if (idx < BB * FF) {
        int b = idx >> 4, f = idx & 15;
        g_y[0][idx] = xb[(b * SS + (SS - 1)) * FF + f];
    }
}

// ---------------- encoder GRU step ----------------
// grid (HH/32, BB/32) = (8,16); 256 threads; thread = (jl, rg) covers 4 batch rows.
__global__ __launch_bounds__(256) void k_enc_step(
    const float* __restrict__ h_in, float* __restrict__ h_out,
    const float* __restrict__ xb,
    const float* __restrict__ bih, const float* __restrict__ bhh, int s)
{
    __shared__ float sh[HH * 36];   // h tile transposed: sh[k][bl], pad 36
    __shared__ float sx[FF * 36];   // x tile transposed
    int tx = threadIdx.x;
    int jb = blockIdx.x * 32, b0 = blockIdx.y * 32;

    #pragma unroll 4
    for (int bl = 0; bl < 32; ++bl)
        sh[tx * 36 + bl] = h_in[(b0 + bl) * HH + tx];
    for (int e = tx; e < FF * 32; e += 256) {
        int f = e >> 5, bl = e & 31;
        sx[f * 36 + bl] = xb[((b0 + bl) * SS + s) * FF + f];
    }
    __syncthreads();

    int jl = tx & 31, rg = tx >> 5;
    int j = jb + jl;
    float ar[4] = {0,0,0,0}, az[4] = {0,0,0,0}, anh[4] = {0,0,0,0}, anx[4] = {0,0,0,0};

    #pragma unroll 4
    for (int k = 0; k < HH; ++k) {
        float4 hv = *reinterpret_cast<const float4*>(&sh[k * 36 + rg * 4]);
        float wr = g_WhhT[k * G3 + j];
        float wz = g_WhhT[k * G3 + HH + j];
        float wn = g_WhhT[k * G3 + 2 * HH + j];
        ar[0] += hv.x * wr; ar[1] += hv.y * wr; ar[2] += hv.z * wr; ar[3] += hv.w * wr;
        az[0] += hv.x * wz; az[1] += hv.y * wz; az[2] += hv.z * wz; az[3] += hv.w * wz;
        anh[0] += hv.x * wn; anh[1] += hv.y * wn; anh[2] += hv.z * wn; anh[3] += hv.w * wn;
    }
    #pragma unroll
    for (int k = 0; k < FF; ++k) {
        float4 xv = *reinterpret_cast<const float4*>(&sx[k * 36 + rg * 4]);
        float wr = g_WihT[k * G3 + j];
        float wz = g_WihT[k * G3 + HH + j];
        float wn = g_WihT[k * G3 + 2 * HH + j];
        ar[0] += xv.x * wr; ar[1] += xv.y * wr; ar[2] += xv.z * wr; ar[3] += xv.w * wr;
        az[0] += xv.x * wz; az[1] += xv.y * wz; az[2] += xv.z * wz; az[3] += xv.w * wz;
        anx[0] += xv.x * wn; anx[1] += xv.y * wn; anx[2] += xv.z * wn; anx[3] += xv.w * wn;
    }

    float br  = bih[j] + bhh[j];
    float bz  = bih[HH + j] + bhh[HH + j];
    float bnx = bih[2 * HH + j];
    float bnh = bhh[2 * HH + j];
    #pragma unroll
    for (int i = 0; i < 4; ++i) {
        int b = b0 + rg * 4 + i;
        float r = sigf(ar[i] + br);
        float z = sigf(az[i] + bz);
        float n = tanhf(anx[i] + bnx + r * (anh[i] + bnh));
        float hold = sh[j * 36 + rg * 4 + i];
        float h2 = (1.f - z) * n + z * hold;
        h_out[b * HH + j] = h2;
        g_eout[(b * SS + s) * HH + j] = h2;
    }
}

// ---------------- decoder attention + softmax + combine (fused) ----------------
// grid BB blocks, 384 threads
__global__ __launch_bounds__(384) void k_attn(
    const float* __restrict__ h_in, const float* __restrict__ y_in,
    const float* __restrict__ attb)
{
    __shared__ float s_in[HH + FF];
    __shared__ float s_attn[SS];
    __shared__ float s_red[12];
    int b = blockIdx.x, tx = threadIdx.x;

    if (tx < HH)            s_in[tx] = h_in[b * HH + tx];
    else if (tx < HH + FF)  s_in[tx] = y_in[b * FF + (tx - HH)];
    __syncthreads();

    float sc = -1e30f;
    if (tx < SS) {
        sc = attb[tx];
        #pragma unroll 4
        for (int k = 0; k < HH + FF; ++k)
            sc += s_in[k] * g_attWT[k * SS + tx];
    }
    // block max
    float v = sc;
    #pragma unroll
    for (int o = 16; o; o >>= 1) v = fmaxf(v, __shfl_xor_sync(0xffffffffu, v, o));
    if ((tx & 31) == 0) s_red[tx >> 5] = v;
    __syncthreads();
    float mx = s_red[0];
    #pragma unroll
    for (int w = 1; w < 12; ++w) mx = fmaxf(mx, s_red[w]);

    float e = (tx < SS) ? __expf(sc - mx) : 0.f;
    if (tx < SS) s_attn[tx] = e;
    float sum = e;
    #pragma unroll
    for (int o = 16; o; o >>= 1) sum += __shfl_xor_sync(0xffffffffu, sum, o);
    __syncthreads();               // everyone done reading s_red (max)
    if ((tx & 31) == 0) s_red[tx >> 5] = sum;
    __syncthreads();
    float tot = 0.f;
    #pragma unroll
    for (int w = 0; w < 12; ++w) tot += s_red[w];
    float inv = 1.f / tot;

    // combine: out[h] = (sum_s attn[s] * eout[b][s][h]) * inv
    if (tx < HH) {
        const float* ep = g_eout + (size_t)b * SS * HH + tx;
        float acc = 0.f;
        #pragma unroll 4
        for (int s2 = 0; s2 < SS; ++s2)
            acc += s_attn[s2] * ep[(size_t)s2 * HH];
        g_comb[b * HH + tx] = acc * inv;
    }
}

// ---------------- decoder GRU step ----------------
// grid (8,16); 256 threads; dynamic smem: 2 * HH*36 floats
__global__ __launch_bounds__(256) void k_dec_gru(
    const float* __restrict__ h_in, float* __restrict__ h_out,
    const float* __restrict__ bih, const float* __restrict__ bhh)
{
    extern __shared__ float dsm[];
    float* sh = dsm;               // h tile  [k][bl]
    float* sc = dsm + HH * 36;     // combine tile
    int tx = threadIdx.x;
    int jb = blockIdx.x * 32, b0 = blockIdx.y * 32;

    #pragma unroll 4
    for (int bl = 0; bl < 32; ++bl) {
        sh[tx * 36 + bl] = h_in[(b0 + bl) * HH + tx];
        sc[tx * 36 + bl] = g_comb[(b0 + bl) * HH + tx];
    }
    __syncthreads();

    int jl = tx & 31, rg = tx >> 5;
    int j = jb + jl;
    float ar[4] = {0,0,0,0}, az[4] = {0,0,0,0}, anh[4] = {0,0,0,0}, anx[4] = {0,0,0,0};

    #pragma unroll 2
    for (int k = 0; k < HH; ++k) {
        float4 hv = *reinterpret_cast<const float4*>(&sh[k * 36 + rg * 4]);
        float4 cv = *reinterpret_cast<const float4*>(&sc[k * 36 + rg * 4]);
        float whr = g_dWhhT[k * G3 + j];
        float whz = g_dWhhT[k * G3 + HH + j];
        float whn = g_dWhhT[k * G3 + 2 * HH + j];
        float wxr = g_dWihT[k * G3 + j];
        float wxz = g_dWihT[k * G3 + HH + j];
        float wxn = g_dWihT[k * G3 + 2 * HH + j];
        ar[0] += hv.x * whr; ar[1] += hv.y * whr; ar[2] += hv.z * whr; ar[3] += hv.w * whr;
        ar[0] += cv.x * wxr; ar[1] += cv.y * wxr; ar[2] += cv.z * wxr; ar[3] += cv.w * wxr;
        az[0] += hv.x * whz; az[1] += hv.y * whz; az[2] += hv.z * whz; az[3] += hv.w * whz;
        az[0] += cv.x * wxz; az[1] += cv.y * wxz; az[2] += cv.z * wxz; az[3] += cv.w * wxz;
        anh[0] += hv.x * whn; anh[1] += hv.y * whn; anh[2] += hv.z * whn; anh[3] += hv.w * whn;
        anx[0] += cv.x * wxn; anx[1] += cv.y * wxn; anx[2] += cv.z * wxn; anx[3] += cv.w * wxn;
    }

    float br  = bih[j] + bhh[j];
    float bz  = bih[HH + j] + bhh[HH + j];
    float bnx = bih[2 * HH + j];
    float bnh = bhh[2 * HH + j];
    #pragma unroll
    for (int i = 0; i < 4; ++i) {
        int b = b0 + rg * 4 + i;
        float r = sigf(ar[i] + br);
        float z = sigf(az[i] + bz);
        float n = tanhf(anx[i] + bnx + r * (anh[i] + bnh));
        float hold = sh[j * 36 + rg * 4 + i];
        float h2 = (1.f - z) * n + z * hold;
        h_out[b * HH + j] = h2;
    }
}

// ---------------- decoder output projection + final linear ----------------
// grid BB/8, 256 threads (8 warps; warp = one batch row)
__global__ __launch_bounds__(256) void k_dec_out(
    const float* __restrict__ h_in, const float* __restrict__ outW,
    const float* __restrict__ outb, const float* __restrict__ linW,
    const float* __restrict__ linb, float* __restrict__ y_out,
    float* __restrict__ dout, int p)
{
    __shared__ float s_o[8][16];
    int w = threadIdx.x >> 5, lane = threadIdx.x & 31;
    int b = blockIdx.x * 8 + w;
    const float* hp = h_in + b * HH;

    #pragma unroll
    for (int f = 0; f < 16; ++f) {
        float acc = 0.f;
        #pragma unroll
        for (int k = lane; k < HH; k += 32) acc += hp[k] * outW[f * HH + k];
        #pragma unroll
        for (int o = 16; o; o >>= 1) acc += __shfl_xor_sync(0xffffffffu, acc, o);
        if (lane == 0) s_o[w][f] = acc;
    }
    __syncwarp();
    if (lane < 16) {
        float vv = s_o[w][lane] + outb[lane];
        s_o[w][lane] = vv;
        y_out[b * FF + lane] = vv;
    }
    __syncwarp();
    if (lane == 0) {
        float fin = linb[0];
        #pragma unroll
        for (int f = 0; f < 16; ++f) fin += s_o[w][f] * linW[f];
        dout[b * PP + p] = fin;
    }
}

// ---------------- launch ----------------
extern "C" void kernel_launch(void* const* d_in, const int* in_sizes, int n_in,
                              void* d_out, int out_size)
{
    const float* xb   = (const float*)d_in[0];
    const float* eWih = (const float*)d_in[1];
    const float* eWhh = (const float*)d_in[2];
    const float* ebih = (const float*)d_in[3];
    const float* ebhh = (const float*)d_in[4];
    const float* attW = (const float*)d_in[5];
    const float* attb = (const float*)d_in[6];
    const float* dWih = (const float*)d_in[7];
    const float* dWhh = (const float*)d_in[8];
    const float* dbih = (const float*)d_in[9];
    const float* dbhh = (const float*)d_in[10];
    const float* outW = (const float*)d_in[11];
    const float* outb = (const float*)d_in[12];
    const float* linW = (const float*)d_in[13];
    const float* linb = (const float*)d_in[14];
    float* dout = (float*)d_out;

    float *pWhhT, *pWihT, *pdWihT, *pdWhhT, *pattWT, *pH, *pY;
    cudaGetSymbolAddress((void**)&pWhhT,  g_WhhT);
    cudaGetSymbolAddress((void**)&pWihT,  g_WihT);
    cudaGetSymbolAddress((void**)&pdWihT, g_dWihT);
    cudaGetSymbolAddress((void**)&pdWhhT, g_dWhhT);
    cudaGetSymbolAddress((void**)&pattWT, g_attWT);
    cudaGetSymbolAddress((void**)&pH,     g_h);
    cudaGetSymbolAddress((void**)&pY,     g_y);
    float* hb[2] = { pH, pH + BB * HH };
    float* yb[2] = { pY, pY + BB * FF };

    // weight transposes + state init (run every call; deterministic)
    k_transpose<<<(G3 * HH + 255) / 256, 256>>>(eWhh, pWhhT, G3, HH);
    k_transpose<<<(G3 * FF + 255) / 256, 256>>>(eWih, pWihT, G3, FF);
    k_transpose<<<(G3 * HH + 255) / 256, 256>>>(dWih, pdWihT, G3, HH);
    k_transpose<<<(G3 * HH + 255) / 256, 256>>>(dWhh, pdWhhT, G3, HH);
    k_transpose<<<(SS * (HH + FF) + 255) / 256, 256>>>(attW, pattWT, SS, HH + FF);
    k_init<<<(BB * HH) / 256, 256>>>(xb);

    // encoder scan
    dim3 egrid(HH / 32, BB / 32);
    for (int s = 0; s < SS; ++s)
        k_enc_step<<<egrid, 256>>>(hb[s & 1], hb[(s + 1) & 1], xb, ebih, ebhh, s);
    // final encoder hidden lands in hb[0] (SS even)

    // decoder scan
    cudaFuncSetAttribute(k_dec_gru, cudaFuncAttributeMaxDynamicSharedMemorySize,
                         2 * HH * 36 * (int)sizeof(float));
    for (int p = 0; p < PP; ++p) {
        k_attn<<<BB, 384>>>(hb[p & 1], yb[p & 1], attb);
        k_dec_gru<<<egrid, 256, 2 * HH * 36 * (int)sizeof(float)>>>(
            hb[p & 1], hb[(p + 1) & 1], dbih, dbhh);
        k_dec_out<<<BB / 8, 256>>>(hb[(p + 1) & 1], outW, outb, linW, linb,
                                   yb[(p + 1) & 1], dout, p);
    }
}

// round 3
// speedup vs baseline: 1.2974x; 1.2974x over previous
#include <cuda_runtime.h>
#include <cuda_fp16.h>
#include <math.h>

#define BB 512
#define SS 336
#define FF 16
#define HH 256
#define PP 48
#define G3 768   // 3*HH
#define AK 272   // HH+FF

// ---------------- scratch (device globals; allocation-free) ----------------
__device__ float  g_h[2][BB*HH];        // ping-pong hidden state
__device__ float  g_y[2][BB*FF];        // ping-pong decoder y
__device__ float  g_comb[BB*HH];        // attention combine output
__device__ float  g_attn[BB*SS];        // normalized attention weights
__device__ __half g_eoutH[(size_t)BB*SS*HH]; // encoder outputs, fp16 (88 MB, L2-resident)
__device__ float  g_WhhT[HH*G3];        // enc Whh transposed: [k][j]
__device__ float  g_WihT[FF*G3];        // enc Wih transposed
__device__ float  g_dWihT[HH*G3];       // dec Wih transposed
__device__ float  g_dWhhT[HH*G3];       // dec Whh transposed
__device__ float  g_attWT[AK*SS];       // att_W transposed: [k][s]

__device__ __forceinline__ float sigf(float x) { return 1.f / (1.f + __expf(-x)); }

// ---------------- combined prep: all transposes in ONE kernel ----------------
#define N1 (G3*HH)
#define N2 (G3*FF)
#define N5 (SS*AK)
__global__ void k_prep(const float* __restrict__ eWhh, const float* __restrict__ eWih,
                       const float* __restrict__ dWih, const float* __restrict__ dWhh,
                       const float* __restrict__ attW)
{
    int idx = blockIdx.x * 256 + threadIdx.x;
    if (idx < N1) {
        int r = idx / HH, c = idx % HH;
        g_WhhT[c * G3 + r] = eWhh[idx];
    } else if (idx < N1 + N2) {
        int i = idx - N1; int r = i / FF, c = i % FF;
        g_WihT[c * G3 + r] = eWih[i];
    } else if (idx < 2*N1 + N2) {
        int i = idx - N1 - N2; int r = i / HH, c = i % HH;
        g_dWihT[c * G3 + r] = dWih[i];
    } else if (idx < 3*N1 + N2) {
        int i = idx - 2*N1 - N2; int r = i / HH, c = i % HH;
        g_dWhhT[c * G3 + r] = dWhh[i];
    } else if (idx < 3*N1 + N2 + N5) {
        int i = idx - 3*N1 - N2; int r = i / AK, c = i % AK;
        g_attWT[c * SS + r] = attW[i];
    }
}

__global__ void k_init(const float* __restrict__ xb) {
    int idx = blockIdx.x * 256 + threadIdx.x;
    if (idx < BB * HH) g_h[0][idx] = 0.f;
    if (idx < BB * FF) {
        int b = idx >> 4, f = idx & 15;
        g_y[0][idx] = xb[(b * SS + (SS - 1)) * FF + f];
    }
}

// ---------------- encoder GRU step (k-split, 512 threads) ----------------
// grid (HH/32, BB/32) = (8,16). Thread (jl, rg, kh): j=jb+jl, 4 batch rows, k-half kh.
// dyn smem: sh[HH*36] h-tile + sx[FF*36] x-tile + sp[16*256] partials
#define ENC_SMEM ((HH*36 + FF*36 + 16*256) * 4)
__global__ __launch_bounds__(512) void k_enc_step(
    const float* __restrict__ h_in, float* __restrict__ h_out,
    const float* __restrict__ xb,
    const float* __restrict__ bih, const float* __restrict__ bhh, int s)
{
    extern __shared__ float dsm[];
    float* sh = dsm;                       // [k][bl] pad 36
    float* sx = dsm + HH * 36;
    float* sp = dsm + HH * 36 + FF * 36;   // partials [c][t256]
    int tx = threadIdx.x;
    int jb = blockIdx.x * 32, b0 = blockIdx.y * 32;

    for (int e = tx; e < HH * 32; e += 512) {
        int bl = e >> 8, k = e & 255;
        sh[k * 36 + bl] = h_in[(b0 + bl) * HH + k];
    }
    if (tx < FF * 32) {
        int f = tx >> 5, bl = tx & 31;
        sx[f * 36 + bl] = xb[((b0 + bl) * SS + s) * FF + f];
    }
    __syncthreads();

    int jl = tx & 31, rg = (tx >> 5) & 7, kh = tx >> 8;
    int j = jb + jl;
    float ar[4] = {0,0,0,0}, az[4] = {0,0,0,0}, an[4] = {0,0,0,0}, ax[4] = {0,0,0,0};

    int kbase = kh * 128;
    #pragma unroll 8
    for (int i = 0; i < 128; ++i) {
        int k = kbase + i;
        float4 hv = *reinterpret_cast<const float4*>(&sh[k * 36 + rg * 4]);
        float wr = g_WhhT[k * G3 + j];
        float wz = g_WhhT[k * G3 + HH + j];
        float wn = g_WhhT[k * G3 + 2 * HH + j];
        ar[0] += hv.x * wr; ar[1] += hv.y * wr; ar[2] += hv.z * wr; ar[3] += hv.w * wr;
        az[0] += hv.x * wz; az[1] += hv.y * wz; az[2] += hv.z * wz; az[3] += hv.w * wz;
        an[0] += hv.x * wn; an[1] += hv.y * wn; an[2] += hv.z * wn; an[3] += hv.w * wn;
    }
    if (kh == 1) {
        #pragma unroll
        for (int f = 0; f < FF; ++f) {
            float4 xv = *reinterpret_cast<const float4*>(&sx[f * 36 + rg * 4]);
            float wr = g_WihT[f * G3 + j];
            float wz = g_WihT[f * G3 + HH + j];
            float wn = g_WihT[f * G3 + 2 * HH + j];
            ar[0] += xv.x * wr; ar[1] += xv.y * wr; ar[2] += xv.z * wr; ar[3] += xv.w * wr;
            az[0] += xv.x * wz; az[1] += xv.y * wz; az[2] += xv.z * wz; az[3] += xv.w * wz;
            ax[0] += xv.x * wn; ax[1] += xv.y * wn; ax[2] += xv.z * wn; ax[3] += xv.w * wn;
        }
        int t = rg * 32 + jl;
        #pragma unroll
        for (int i = 0; i < 4; ++i) {
            sp[(i     ) * 256 + t] = ar[i];
            sp[(4  + i) * 256 + t] = az[i];
            sp[(8  + i) * 256 + t] = an[i];
            sp[(12 + i) * 256 + t] = ax[i];
        }
    }
    __syncthreads();
    if (kh == 0) {
        int t = rg * 32 + jl;
        #pragma unroll
        for (int i = 0; i < 4; ++i) {
            ar[i] += sp[(i     ) * 256 + t];
            az[i] += sp[(4  + i) * 256 + t];
            an[i] += sp[(8  + i) * 256 + t];
            ax[i] += sp[(12 + i) * 256 + t];
        }
        float br  = bih[j] + bhh[j];
        float bz  = bih[HH + j] + bhh[HH + j];
        float bnx = bih[2 * HH + j];
        float bnh = bhh[2 * HH + j];
        #pragma unroll
        for (int i = 0; i < 4; ++i) {
            int bl = rg * 4 + i, b = b0 + bl;
            float r = sigf(ar[i] + br);
            float z = sigf(az[i] + bz);
            float n = tanhf(ax[i] + bnx + r * (an[i] + bnh));
            float hold = sh[j * 36 + bl];
            float h2 = (1.f - z) * n + z * hold;
            h_out[b * HH + j] = h2;
            g_eoutH[((size_t)b * SS + s) * HH + j] = __float2half(h2);
        }
    }
}

// ---------------- decoder attention scores + softmax (8 rows/block) ----------------
// grid BB/8 = 64 blocks, 512 threads
__global__ __launch_bounds__(512) void k_score(
    const float* __restrict__ h_in, const float* __restrict__ y_in,
    const float* __restrict__ attb)
{
    __shared__ float s_in[8 * AK];
    __shared__ float sc[8 * SS];
    __shared__ float s_inv[8];
    int tx = threadIdx.x, b0 = blockIdx.x * 8;

    for (int e = tx; e < 8 * AK; e += 512) {
        int r = e / AK, k = e % AK;
        s_in[e] = (k < HH) ? h_in[(b0 + r) * HH + k] : y_in[(b0 + r) * FF + (k - HH)];
    }
    __syncthreads();

    if (tx < SS) {
        float acc[8];
        float b = attb[tx];
        #pragma unroll
        for (int r = 0; r < 8; ++r) acc[r] = b;
        for (int k = 0; k < AK; ++k) {
            float w = g_attWT[k * SS + tx];
            #pragma unroll
            for (int r = 0; r < 8; ++r) acc[r] += s_in[r * AK + k] * w;
        }
        #pragma unroll
        for (int r = 0; r < 8; ++r) sc[r * SS + tx] = acc[r];
    }
    __syncthreads();

    int w = tx >> 5, lane = tx & 31;
    if (w < 8) {
        float mx = -1e30f;
        for (int s2 = lane; s2 < SS; s2 += 32) mx = fmaxf(mx, sc[w * SS + s2]);
        #pragma unroll
        for (int o = 16; o; o >>= 1) mx = fmaxf(mx, __shfl_xor_sync(0xffffffffu, mx, o));
        float sum = 0.f;
        for (int s2 = lane; s2 < SS; s2 += 32) {
            float e = __expf(sc[w * SS + s2] - mx);
            sc[w * SS + s2] = e;
            sum += e;
        }
        #pragma unroll
        for (int o = 16; o; o >>= 1) sum += __shfl_xor_sync(0xffffffffu, sum, o);
        if (lane == 0) s_inv[w] = 1.f / sum;
    }
    __syncthreads();

    for (int e = tx; e < 8 * SS; e += 512) {
        int r = e / SS, s2 = e % SS;
        g_attn[(b0 + r) * SS + s2] = sc[e] * s_inv[r];
    }
}

// ---------------- decoder combine (one block per batch row) ----------------
// grid BB, 256 threads: 128 h2-cols x 2 s-halves. eout is fp16, L2-resident.
__global__ __launch_bounds__(256) void k_combine()
{
    __shared__ float sa[SS];
    __shared__ float pcx[128], pcy[128];
    int b = blockIdx.x, tx = threadIdx.x;
    for (int e = tx; e < SS; e += 256) sa[e] = g_attn[b * SS + e];
    __syncthreads();

    int hi = tx & 127, half = tx >> 7;
    float accx = 0.f, accy = 0.f;
    const __half2* ep = reinterpret_cast<const __half2*>(g_eoutH + (size_t)b * SS * HH) + hi;
    int s0 = half * (SS / 2);
    #pragma unroll 4
    for (int s2 = s0; s2 < s0 + SS / 2; ++s2) {
        float2 v = __half22float2(ep[(size_t)s2 * (HH / 2)]);
        float a = sa[s2];
        accx += a * v.x;
        accy += a * v.y;
    }
    if (half == 1) { pcx[hi] = accx; pcy[hi] = accy; }
    __syncthreads();
    if (half == 0) {
        g_comb[b * HH + 2 * hi]     = accx + pcx[hi];
        g_comb[b * HH + 2 * hi + 1] = accy + pcy[hi];
    }
}

// ---------------- decoder GRU step (k-split, 512 threads) ----------------
#define DEC_SMEM ((2*HH*36 + 16*256) * 4)
__global__ __launch_bounds__(512) void k_dec_gru(
    const float* __restrict__ h_in, float* __restrict__ h_out,
    const float* __restrict__ bih, const float* __restrict__ bhh)
{
    extern __shared__ float dsm[];
    float* sh = dsm;                 // h tile  [k][bl]
    float* sc = dsm + HH * 36;       // combine tile
    float* sp = dsm + 2 * HH * 36;   // partials
    int tx = threadIdx.x;
    int jb = blockIdx.x * 32, b0 = blockIdx.y * 32;

    for (int e = tx; e < HH * 32; e += 512) {
        int bl = e >> 8, k = e & 255;
        sh[k * 36 + bl] = h_in[(b0 + bl) * HH + k];
        sc[k * 36 + bl] = g_comb[(b0 + bl) * HH + k];
    }
    __syncthreads();

    int jl = tx & 31, rg = (tx >> 5) & 7, kh = tx >> 8;
    int j = jb + jl;
    float ar[4] = {0,0,0,0}, az[4] = {0,0,0,0}, an[4] = {0,0,0,0}, ax[4] = {0,0,0,0};

    int kbase = kh * 128;
    #pragma unroll 4
    for (int i = 0; i < 128; ++i) {
        int k = kbase + i;
        float4 hv = *reinterpret_cast<const float4*>(&sh[k * 36 + rg * 4]);
        float4 cv = *reinterpret_cast<const float4*>(&sc[k * 36 + rg * 4]);
        float whr = g_dWhhT[k * G3 + j];
        float whz = g_dWhhT[k * G3 + HH + j];
        float whn = g_dWhhT[k * G3 + 2 * HH + j];
        float wxr = g_dWihT[k * G3 + j];
        float wxz = g_dWihT[k * G3 + HH + j];
        float wxn = g_dWihT[k * G3 + 2 * HH + j];
        ar[0] += hv.x * whr + cv.x * wxr; ar[1] += hv.y * whr + cv.y * wxr;
        ar[2] += hv.z * whr + cv.z * wxr; ar[3] += hv.w * whr + cv.w * wxr;
        az[0] += hv.x * whz + cv.x * wxz; az[1] += hv.y * whz + cv.y * wxz;
        az[2] += hv.z * whz + cv.z * wxz; az[3] += hv.w * whz + cv.w * wxz;
        an[0] += hv.x * whn; an[1] += hv.y * whn; an[2] += hv.z * whn; an[3] += hv.w * whn;
        ax[0] += cv.x * wxn; ax[1] += cv.y * wxn; ax[2] += cv.z * wxn; ax[3] += cv.w * wxn;
    }
    if (kh == 1) {
        int t = rg * 32 + jl;
        #pragma unroll
        for (int i = 0; i < 4; ++i) {
            sp[(i     ) * 256 + t] = ar[i];
            sp[(4  + i) * 256 + t] = az[i];
            sp[(8  + i) * 256 + t] = an[i];
            sp[(12 + i) * 256 + t] = ax[i];
        }
    }
    __syncthreads();
    if (kh == 0) {
        int t = rg * 32 + jl;
        #pragma unroll
        for (int i = 0; i < 4; ++i) {
            ar[i] += sp[(i     ) * 256 + t];
            az[i] += sp[(4  + i) * 256 + t];
            an[i] += sp[(8  + i) * 256 + t];
            ax[i] += sp[(12 + i) * 256 + t];
        }
        float br  = bih[j] + bhh[j];
        float bz  = bih[HH + j] + bhh[HH + j];
        float bnx = bih[2 * HH + j];
        float bnh = bhh[2 * HH + j];
        #pragma unroll
        for (int i = 0; i < 4; ++i) {
            int bl = rg * 4 + i, b = b0 + bl;
            float r = sigf(ar[i] + br);
            float z = sigf(az[i] + bz);
            float n = tanhf(ax[i] + bnx + r * (an[i] + bnh));
            float hold = sh[j * 36 + bl];
            float h2 = (1.f - z) * n + z * hold;
            h_out[b * HH + j] = h2;
        }
    }
}

// ---------------- decoder output projection + final linear ----------------
__global__ __launch_bounds__(256) void k_dec_out(
    const float* __restrict__ h_in, const float* __restrict__ outW,
    const float* __restrict__ outb, const float* __restrict__ linW,
    const float* __restrict__ linb, float* __restrict__ y_out,
    float* __restrict__ dout, int p)
{
    __shared__ float s_o[8][16];
    int w = threadIdx.x >> 5, lane = threadIdx.x & 31;
    int b = blockIdx.x * 8 + w;
    const float* hp = h_in + b * HH;

    #pragma unroll
    for (int f = 0; f < 16; ++f) {
        float acc = 0.f;
        #pragma unroll
        for (int k = lane; k < HH; k += 32) acc += hp[k] * outW[f * HH + k];
        #pragma unroll
        for (int o = 16; o; o >>= 1) acc += __shfl_xor_sync(0xffffffffu, acc, o);
        if (lane == 0) s_o[w][f] = acc;
    }
    __syncwarp();
    if (lane < 16) {
        float vv = s_o[w][lane] + outb[lane];
        s_o[w][lane] = vv;
        y_out[b * FF + lane] = vv;
    }
    __syncwarp();
    if (lane == 0) {
        float fin = linb[0];
        #pragma unroll
        for (int f = 0; f < 16; ++f) fin += s_o[w][f] * linW[f];
        dout[b * PP + p] = fin;
    }
}

// ---------------- launch ----------------
extern "C" void kernel_launch(void* const* d_in, const int* in_sizes, int n_in,
                              void* d_out, int out_size)
{
    const float* xb   = (const float*)d_in[0];
    const float* eWih = (const float*)d_in[1];
    const float* eWhh = (const float*)d_in[2];
    const float* ebih = (const float*)d_in[3];
    const float* ebhh = (const float*)d_in[4];
    const float* attW = (const float*)d_in[5];
    const float* attb = (const float*)d_in[6];
    const float* dWih = (const float*)d_in[7];
    const float* dWhh = (const float*)d_in[8];
    const float* dbih = (const float*)d_in[9];
    const float* dbhh = (const float*)d_in[10];
    const float* outW = (const float*)d_in[11];
    const float* outb = (const float*)d_in[12];
    const float* linW = (const float*)d_in[13];
    const float* linb = (const float*)d_in[14];
    float* dout = (float*)d_out;

    float *pH, *pY;
    cudaGetSymbolAddress((void**)&pH, g_h);
    cudaGetSymbolAddress((void**)&pY, g_y);
    float* hb[2] = { pH, pH + BB * HH };
    float* yb[2] = { pY, pY + BB * FF };

    cudaFuncSetAttribute(k_enc_step, cudaFuncAttributeMaxDynamicSharedMemorySize, ENC_SMEM);
    cudaFuncSetAttribute(k_dec_gru,  cudaFuncAttributeMaxDynamicSharedMemorySize, DEC_SMEM);

    const int prep_n = 3 * N1 + N2 + N5;
    k_prep<<<(prep_n + 255) / 256, 256>>>(eWhh, eWih, dWih, dWhh, attW);
    k_init<<<(BB * HH) / 256, 256>>>(xb);

    dim3 egrid(HH / 32, BB / 32);
    for (int s = 0; s < SS; ++s)
        k_enc_step<<<egrid, 512, ENC_SMEM>>>(hb[s & 1], hb[(s + 1) & 1], xb, ebih, ebhh, s);
    // SS even: final encoder hidden in hb[0]

    for (int p = 0; p < PP; ++p) {
        k_score<<<BB / 8, 512>>>(hb[p & 1], yb[p & 1], attb);
        k_combine<<<BB, 256>>>();
        k_dec_gru<<<egrid, 512, DEC_SMEM>>>(hb[p & 1], hb[(p + 1) & 1], dbih, dbhh);
        k_dec_out<<<BB / 8, 256>>>(hb[(p + 1) & 1], outW, outb, linW, linb,
                                   yb[(p + 1) & 1], dout, p);
    }
}

// round 4
// speedup vs baseline: 1.5731x; 1.2125x over previous
#include <cuda_runtime.h>
#include <cuda_fp16.h>
#include <math.h>

#define BB 512
#define SS 336
#define FF 16
#define HH 256
#define PP 48
#define G3 768   // 3*HH
#define AK 272   // HH+FF

// ---------------- scratch (device globals; allocation-free) ----------------
__device__ float  g_h[2][BB*HH];        // ping-pong hidden state
__device__ float  g_y[2][BB*FF];        // ping-pong decoder y
__device__ float  g_comb[BB*HH];        // attention combine output
__device__ float  g_attn[BB*SS];        // normalized attention weights
__device__ __half g_eoutH[(size_t)BB*SS*HH]; // encoder outputs fp16 (88 MB)
__device__ float  g_dWihT[HH*G3];       // dec Wih transposed
__device__ float  g_dWhhT[HH*G3];       // dec Whh transposed
__device__ float  g_attWT[AK*SS];       // att_W transposed: [k][s]
__device__ int    g_bar[16];            // per-by-group arrival counters

__device__ __forceinline__ float sigf(float x) { return 1.f / (1.f + __expf(-x)); }

// ---------------- prep: decoder weight transposes ----------------
#define N1 (G3*HH)
#define N5 (SS*AK)
__global__ void k_prep(const float* __restrict__ dWih, const float* __restrict__ dWhh,
                       const float* __restrict__ attW)
{
    int idx = blockIdx.x * 256 + threadIdx.x;
    if (idx < N1) {
        int r = idx / HH, c = idx % HH;
        g_dWihT[c * G3 + r] = dWih[idx];
    } else if (idx < 2 * N1) {
        int i = idx - N1; int r = i / HH, c = i % HH;
        g_dWhhT[c * G3 + r] = dWhh[i];
    } else if (idx < 2 * N1 + N5) {
        int i = idx - 2 * N1; int r = i / AK, c = i % AK;
        g_attWT[c * SS + r] = attW[i];
    }
}

__global__ void k_init(const float* __restrict__ xb) {
    int idx = blockIdx.x * 256 + threadIdx.x;
    if (idx < BB * FF) {
        int b = idx >> 4, f = idx & 15;
        g_y[0][idx] = xb[(b * SS + (SS - 1)) * FF + f];
    }
    if (idx < 16) g_bar[idx] = 0;
}

// ---------------- persistent encoder ----------------
// grid (8,16) = 128 blocks, 512 threads, 1 block/SM.
// Block (jx,by): j-slice [jx*32, jx*32+32), batch tile [by*32, by*32+32).
// Weights for the j-slice live in smem for all 336 steps.
// smem floats: sw 24576 | swi 1536 | sh 9216 | sx 576 | sp 4096  = 40000 (160 KB)
#define ENC_SMEM (40000 * 4)
__global__ __launch_bounds__(512) void k_encoder(
    const float* __restrict__ xb,
    const float* __restrict__ Wih, const float* __restrict__ Whh,
    const float* __restrict__ bih, const float* __restrict__ bhh)
{
    extern __shared__ float sm[];
    float* sw  = sm;            // [(k*3+g)*32 + jl]
    float* swi = sm + 24576;    // [(k*3+g)*32 + jl], k<16
    float* sh  = sm + 26112;    // [k*36 + bl]
    float* sx  = sm + 35328;    // [f*36 + bl]
    float* sp  = sm + 35904;    // partials [c*256 + t]

    int tx = threadIdx.x, jl = tx & 31, grp = tx >> 5;
    int jb = blockIdx.x * 32, by = blockIdx.y, b0 = by * 32;
    int j = jb + jl;

    // ---- one-time: load weight slice into smem (lanes = jl: conflict-free STS) ----
    for (int t = grp; t < 192; t += 16) {          // 3 gates x 64 k-quads
        int g = t >> 6, kq = t & 63;
        float4 v = *reinterpret_cast<const float4*>(&Whh[(size_t)(g * HH + j) * HH + 4 * kq]);
        sw[((4 * kq + 0) * 3 + g) * 32 + jl] = v.x;
        sw[((4 * kq + 1) * 3 + g) * 32 + jl] = v.y;
        sw[((4 * kq + 2) * 3 + g) * 32 + jl] = v.z;
        sw[((4 * kq + 3) * 3 + g) * 32 + jl] = v.w;
    }
    if (grp < 12) {                                 // 3 gates x 4 k-quads (FF=16)
        int g = grp >> 2, kq = grp & 3;
        float4 v = *reinterpret_cast<const float4*>(&Wih[(size_t)(g * HH + j) * FF + 4 * kq]);
        swi[((4 * kq + 0) * 3 + g) * 32 + jl] = v.x;
        swi[((4 * kq + 1) * 3 + g) * 32 + jl] = v.y;
        swi[((4 * kq + 2) * 3 + g) * 32 + jl] = v.z;
        swi[((4 * kq + 3) * 3 + g) * 32 + jl] = v.w;
    }
    // biases (used by kh==0 threads)
    float br  = bih[j] + bhh[j];
    float bz  = bih[HH + j] + bhh[HH + j];
    float bnx = bih[2 * HH + j];
    float bnh = bhh[2 * HH + j];

    // h(0) = 0; x tile for s=0
    for (int e = tx; e < HH * 36; e += 512) sh[e] = 0.f;
    {
        int f = grp, bl = jl;
        sx[f * 36 + bl] = xb[((b0 + bl) * SS + 0) * FF + f];
    }
    __syncthreads();

    int kh = tx >> 8, rg = (tx >> 5) & 7;
    int kbase = kh << 7;
    int t256 = rg * 32 + jl;

    for (int s = 0; s < SS; ++s) {
        float ar[4] = {0,0,0,0}, az[4] = {0,0,0,0}, an[4] = {0,0,0,0}, ax[4] = {0,0,0,0};

        #pragma unroll 4
        for (int i = 0; i < 128; ++i) {
            int k = kbase + i;
            float4 hv = *reinterpret_cast<const float4*>(&sh[k * 36 + rg * 4]);
            const float* wp = &sw[k * 96 + jl];
            float wr = wp[0], wz = wp[32], wn = wp[64];
            ar[0] += hv.x * wr; ar[1] += hv.y * wr; ar[2] += hv.z * wr; ar[3] += hv.w * wr;
            az[0] += hv.x * wz; az[1] += hv.y * wz; az[2] += hv.z * wz; az[3] += hv.w * wz;
            an[0] += hv.x * wn; an[1] += hv.y * wn; an[2] += hv.z * wn; an[3] += hv.w * wn;
        }
        if (kh == 1) {
            #pragma unroll
            for (int k = 0; k < FF; ++k) {
                float4 xv = *reinterpret_cast<const float4*>(&sx[k * 36 + rg * 4]);
                const float* wp = &swi[k * 96 + jl];
                float wr = wp[0], wz = wp[32], wn = wp[64];
                ar[0] += xv.x * wr; ar[1] += xv.y * wr; ar[2] += xv.z * wr; ar[3] += xv.w * wr;
                az[0] += xv.x * wz; az[1] += xv.y * wz; az[2] += xv.z * wz; az[3] += xv.w * wz;
                ax[0] += xv.x * wn; ax[1] += xv.y * wn; ax[2] += xv.z * wn; ax[3] += xv.w * wn;
            }
            #pragma unroll
            for (int i = 0; i < 4; ++i) {
                sp[(i     ) * 256 + t256] = ar[i];
                sp[(4  + i) * 256 + t256] = az[i];
                sp[(8  + i) * 256 + t256] = an[i];
                sp[(12 + i) * 256 + t256] = ax[i];
            }
        }
        __syncthreads();
        if (kh == 0) {
            int nx = (s + 1) & 1;
            #pragma unroll
            for (int i = 0; i < 4; ++i) {
                ar[i] += sp[(i     ) * 256 + t256];
                az[i] += sp[(4  + i) * 256 + t256];
                an[i] += sp[(8  + i) * 256 + t256];
                ax[i] += sp[(12 + i) * 256 + t256];
            }
            #pragma unroll
            for (int i = 0; i < 4; ++i) {
                int bl = rg * 4 + i, b = b0 + bl;
                float r = sigf(ar[i] + br);
                float z = sigf(az[i] + bz);
                float n = tanhf(ax[i] + bnx + r * (an[i] + bnh));
                float hold = sh[j * 36 + bl];
                float h2 = (1.f - z) * n + z * hold;
                g_h[nx][b * HH + j] = h2;
                g_eoutH[((size_t)b * SS + s) * HH + j] = __float2half(h2);
            }
            __threadfence();
        }
        __syncthreads();
        if (s == SS - 1) break;

        // per-by-group barrier: 8 j-blocks must finish step s
        if (tx == 0) {
            atomicAdd(&g_bar[by], 1);
            volatile int* vb = &g_bar[by];
            while (*vb < 8 * (s + 1)) { }
            __threadfence();
        }
        __syncthreads();

        // reload h tile (ld.cg: bypass stale L1) + next x tile
        {
            int nx = (s + 1) & 1;
            #pragma unroll
            for (int q = 0; q < 4; ++q) {
                int kq = grp * 4 + q;
                float4 hv = __ldcg(reinterpret_cast<const float4*>(
                    &g_h[nx][(b0 + jl) * HH + 4 * kq]));
                sh[(4 * kq + 0) * 36 + jl] = hv.x;
                sh[(4 * kq + 1) * 36 + jl] = hv.y;
                sh[(4 * kq + 2) * 36 + jl] = hv.z;
                sh[(4 * kq + 3) * 36 + jl] = hv.w;
            }
            sx[grp * 36 + jl] = xb[((b0 + jl) * SS + (s + 1)) * FF + grp];
        }
        __syncthreads();
    }
}

// ---------------- decoder attention scores + softmax (8 rows/block) ----------------
__global__ __launch_bounds__(512) void k_score(
    const float* __restrict__ h_in, const float* __restrict__ y_in,
    const float* __restrict__ attb)
{
    __shared__ float s_in[8 * AK];
    __shared__ float sc[8 * SS];
    __shared__ float s_inv[8];
    int tx = threadIdx.x, b0 = blockIdx.x * 8;

    for (int e = tx; e < 8 * AK; e += 512) {
        int r = e / AK, k = e % AK;
        s_in[e] = (k < HH) ? h_in[(b0 + r) * HH + k] : y_in[(b0 + r) * FF + (k - HH)];
    }
    __syncthreads();

    if (tx < SS) {
        float acc[8];
        float b = attb[tx];
        #pragma unroll
        for (int r = 0; r < 8; ++r) acc[r] = b;
        for (int k = 0; k < AK; ++k) {
            float w = g_attWT[k * SS + tx];
            #pragma unroll
            for (int r = 0; r < 8; ++r) acc[r] += s_in[r * AK + k] * w;
        }
        #pragma unroll
        for (int r = 0; r < 8; ++r) sc[r * SS + tx] = acc[r];
    }
    __syncthreads();

    int w = tx >> 5, lane = tx & 31;
    if (w < 8) {
        float mx = -1e30f;
        for (int s2 = lane; s2 < SS; s2 += 32) mx = fmaxf(mx, sc[w * SS + s2]);
        #pragma unroll
        for (int o = 16; o; o >>= 1) mx = fmaxf(mx, __shfl_xor_sync(0xffffffffu, mx, o));
        float sum = 0.f;
        for (int s2 = lane; s2 < SS; s2 += 32) {
            float e = __expf(sc[w * SS + s2] - mx);
            sc[w * SS + s2] = e;
            sum += e;
        }
        #pragma unroll
        for (int o = 16; o; o >>= 1) sum += __shfl_xor_sync(0xffffffffu, sum, o);
        if (lane == 0) s_inv[w] = 1.f / sum;
    }
    __syncthreads();

    for (int e = tx; e < 8 * SS; e += 512) {
        int r = e / SS, s2 = e % SS;
        g_attn[(b0 + r) * SS + s2] = sc[e] * s_inv[r];
    }
}

// ---------------- decoder combine ----------------
__global__ __launch_bounds__(256) void k_combine()
{
    __shared__ float sa[SS];
    __shared__ float pcx[128], pcy[128];
    int b = blockIdx.x, tx = threadIdx.x;
    for (int e = tx; e < SS; e += 256) sa[e] = g_attn[b * SS + e];
    __syncthreads();

    int hi = tx & 127, half = tx >> 7;
    float accx = 0.f, accy = 0.f;
    const __half2* ep = reinterpret_cast<const __half2*>(g_eoutH + (size_t)b * SS * HH) + hi;
    int s0 = half * (SS / 2);
    #pragma unroll 4
    for (int s2 = s0; s2 < s0 + SS / 2; ++s2) {
        float2 v = __half22float2(ep[(size_t)s2 * (HH / 2)]);
        float a = sa[s2];
        accx += a * v.x;
        accy += a * v.y;
    }
    if (half == 1) { pcx[hi] = accx; pcy[hi] = accy; }
    __syncthreads();
    if (half == 0) {
        g_comb[b * HH + 2 * hi]     = accx + pcx[hi];
        g_comb[b * HH + 2 * hi + 1] = accy + pcy[hi];
    }
}

// ---------------- decoder GRU step (k-split, 512 threads) ----------------
#define DEC_SMEM ((2*HH*36 + 16*256) * 4)
__global__ __launch_bounds__(512) void k_dec_gru(
    const float* __restrict__ h_in, float* __restrict__ h_out,
    const float* __restrict__ bih, const float* __restrict__ bhh)
{
    extern __shared__ float dsm[];
    float* sh = dsm;
    float* sc = dsm + HH * 36;
    float* sp = dsm + 2 * HH * 36;
    int tx = threadIdx.x;
    int jb = blockIdx.x * 32, b0 = blockIdx.y * 32;

    for (int e = tx; e < HH * 32; e += 512) {
        int bl = e >> 8, k = e & 255;
        sh[k * 36 + bl] = h_in[(b0 + bl) * HH + k];
        sc[k * 36 + bl] = g_comb[(b0 + bl) * HH + k];
    }
    __syncthreads();

    int jl = tx & 31, rg = (tx >> 5) & 7, kh = tx >> 8;
    int j = jb + jl;
    float ar[4] = {0,0,0,0}, az[4] = {0,0,0,0}, an[4] = {0,0,0,0}, ax[4] = {0,0,0,0};

    int kbase = kh * 128;
    #pragma unroll 4
    for (int i = 0; i < 128; ++i) {
        int k = kbase + i;
        float4 hv = *reinterpret_cast<const float4*>(&sh[k * 36 + rg * 4]);
        float4 cv = *reinterpret_cast<const float4*>(&sc[k * 36 + rg * 4]);
        float whr = g_dWhhT[k * G3 + j];
        float whz = g_dWhhT[k * G3 + HH + j];
        float whn = g_dWhhT[k * G3 + 2 * HH + j];
        float wxr = g_dWihT[k * G3 + j];
        float wxz = g_dWihT[k * G3 + HH + j];
        float wxn = g_dWihT[k * G3 + 2 * HH + j];
        ar[0] += hv.x * whr + cv.x * wxr; ar[1] += hv.y * whr + cv.y * wxr;
        ar[2] += hv.z * whr + cv.z * wxr; ar[3] += hv.w * whr + cv.w * wxr;
        az[0] += hv.x * whz + cv.x * wxz; az[1] += hv.y * whz + cv.y * wxz;
        az[2] += hv.z * whz + cv.z * wxz; az[3] += hv.w * whz + cv.w * wxz;
        an[0] += hv.x * whn; an[1] += hv.y * whn; an[2] += hv.z * whn; an[3] += hv.w * whn;
        ax[0] += cv.x * wxn; ax[1] += cv.y * wxn; ax[2] += cv.z * wxn; ax[3] += cv.w * wxn;
    }
    if (kh == 1) {
        int t = rg * 32 + jl;
        #pragma unroll
        for (int i = 0; i < 4; ++i) {
            sp[(i     ) * 256 + t] = ar[i];
            sp[(4  + i) * 256 + t] = az[i];
            sp[(8  + i) * 256 + t] = an[i];
            sp[(12 + i) * 256 + t] = ax[i];
        }
    }
    __syncthreads();
    if (kh == 0) {
        int t = rg * 32 + jl;
        #pragma unroll
        for (int i = 0; i < 4; ++i) {
            ar[i] += sp[(i     ) * 256 + t];
            az[i] += sp[(4  + i) * 256 + t];
            an[i] += sp[(8  + i) * 256 + t];
            ax[i] += sp[(12 + i) * 256 + t];
        }
        float br  = bih[j] + bhh[j];
        float bz  = bih[HH + j] + bhh[HH + j];
        float bnx = bih[2 * HH + j];
        float bnh = bhh[2 * HH + j];
        #pragma unroll
        for (int i = 0; i < 4; ++i) {
            int bl = rg * 4 + i, b = b0 + bl;
            float r = sigf(ar[i] + br);
            float z = sigf(az[i] + bz);
            float n = tanhf(ax[i] + bnx + r * (an[i] + bnh));
            float hold = sh[j * 36 + bl];
            float h2 = (1.f - z) * n + z * hold;
            h_out[b * HH + j] = h2;
        }
    }
}

// ---------------- decoder output projection + final linear ----------------
__global__ __launch_bounds__(256) void k_dec_out(
    const float* __restrict__ h_in, const float* __restrict__ outW,
    const float* __restrict__ outb, const float* __restrict__ linW,
    const float* __restrict__ linb, float* __restrict__ y_out,
    float* __restrict__ dout, int p)
{
    __shared__ float s_o[8][16];
    int w = threadIdx.x >> 5, lane = threadIdx.x & 31;
    int b = blockIdx.x * 8 + w;
    const float* hp = h_in + b * HH;

    #pragma unroll
    for (int f = 0; f < 16; ++f) {
        float acc = 0.f;
        #pragma unroll
        for (int k = lane; k < HH; k += 32) acc += hp[k] * outW[f * HH + k];
        #pragma unroll
        for (int o = 16; o; o >>= 1) acc += __shfl_xor_sync(0xffffffffu, acc, o);
        if (lane == 0) s_o[w][f] = acc;
    }
    __syncwarp();
    if (lane < 16) {
        float vv = s_o[w][lane] + outb[lane];
        s_o[w][lane] = vv;
        y_out[b * FF + lane] = vv;
    }
    __syncwarp();
    if (lane == 0) {
        float fin = linb[0];
        #pragma unroll
        for (int f = 0; f < 16; ++f) fin += s_o[w][f] * linW[f];
        dout[b * PP + p] = fin;
    }
}

// ---------------- launch ----------------
extern "C" void kernel_launch(void* const* d_in, const int* in_sizes, int n_in,
                              void* d_out, int out_size)
{
    const float* xb   = (const float*)d_in[0];
    const float* eWih = (const float*)d_in[1];
    const float* eWhh = (const float*)d_in[2];
    const float* ebih = (const float*)d_in[3];
    const float* ebhh = (const float*)d_in[4];
    const float* attW = (const float*)d_in[5];
    const float* attb = (const float*)d_in[6];
    const float* dWih = (const float*)d_in[7];
    const float* dWhh = (const float*)d_in[8];
    const float* dbih = (const float*)d_in[9];
    const float* dbhh = (const float*)d_in[10];
    const float* outW = (const float*)d_in[11];
    const float* outb = (const float*)d_in[12];
    const float* linW = (const float*)d_in[13];
    const float* linb = (const float*)d_in[14];
    float* dout = (float*)d_out;

    float *pH, *pY;
    cudaGetSymbolAddress((void**)&pH, g_h);
    cudaGetSymbolAddress((void**)&pY, g_y);
    float* hb[2] = { pH, pH + BB * HH };
    float* yb[2] = { pY, pY + BB * FF };

    cudaFuncSetAttribute(k_encoder, cudaFuncAttributeMaxDynamicSharedMemorySize, ENC_SMEM);
    cudaFuncSetAttribute(k_dec_gru, cudaFuncAttributeMaxDynamicSharedMemorySize, DEC_SMEM);

    const int prep_n = 2 * N1 + N5;
    k_prep<<<(prep_n + 255) / 256, 256>>>(dWih, dWhh, attW);
    k_init<<<32, 256>>>(xb);

    // persistent encoder: one launch for all 336 steps
    k_encoder<<<dim3(8, 16), 512, ENC_SMEM>>>(xb, eWih, eWhh, ebih, ebhh);
    // SS even: final encoder hidden in g_h[0]

    dim3 egrid(HH / 32, BB / 32);
    for (int p = 0; p < PP; ++p) {
        k_score<<<BB / 8, 512>>>(hb[p & 1], yb[p & 1], attb);
        k_combine<<<BB, 256>>>();
        k_dec_gru<<<egrid, 512, DEC_SMEM>>>(hb[p & 1], hb[(p + 1) & 1], dbih, dbhh);
        k_dec_out<<<BB / 8, 256>>>(hb[(p + 1) & 1], outW, outb, linW, linb,
                                   yb[(p + 1) & 1], dout, p);
    }
}

// round 6
// speedup vs baseline: 3.7463x; 2.3815x over previous
#include <cuda_runtime.h>
#include <cuda_fp16.h>
#include <math.h>

#define BB 512
#define SS 336
#define FF 16
#define HH 256
#define PP 48
#define AK 272   // HH+FF

// ---------------- prepared weights (device globals; allocation-free) ----------------
__device__ float4 g_eW4 [64*3*256];   // enc Whh: [k4][gate][j] float4 over k      (786 KB)
__device__ float4 g_eWi4[ 4*3*256];   // enc Wih: [k4][gate][j] float4 over k      ( 48 KB)
__device__ uint4  g_dWh8[32*3*256];   // dec Whh fp16: [k8][gate][j] 8 halves/k8   (393 KB)
__device__ uint4  g_dWi8[32*3*256];   // dec Wih fp16: same                        (393 KB)
__device__ __half g_aWh [AK*SS];      // att_W fp16 transposed [k][s]              (179 KB)
__device__ __half g_eoutH[(size_t)BB*SS*HH]; // encoder outputs fp16 (88 MB, L2-resident)

__device__ __forceinline__ float sigf(float x) { return 1.f / (1.f + __expf(-x)); }

// ---------------- prep: one-time weight transforms ----------------
#define EW_F   (64*3*256*4)
#define EWI_F  (4*3*256*4)
#define DW_H   (32*3*256*8)
#define AW_H   (AK*SS)
#define PREP_N (EW_F + EWI_F + 2*DW_H + AW_H)

__global__ void k_prep(const float* __restrict__ eWih, const float* __restrict__ eWhh,
                       const float* __restrict__ dWih, const float* __restrict__ dWhh,
                       const float* __restrict__ attW)
{
    int idx = blockIdx.x * 256 + threadIdx.x;
    if (idx < EW_F) {
        int q = idx >> 2, c = idx & 3;
        int j = q & 255, g = (q >> 8) % 3, k4 = q / 768;
        ((float*)g_eW4)[idx] = eWhh[(g*HH + j)*HH + 4*k4 + c];
    } else if (idx < EW_F + EWI_F) {
        int i = idx - EW_F, q = i >> 2, c = i & 3;
        int j = q & 255, g = (q >> 8) % 3, k4 = q / 768;
        ((float*)g_eWi4)[i] = eWih[(g*HH + j)*FF + 4*k4 + c];
    } else if (idx < EW_F + EWI_F + DW_H) {
        int i = idx - EW_F - EWI_F, q = i >> 3, c = i & 7;
        int j = q & 255, g = (q >> 8) % 3, k8 = q / 768;
        ((__half*)g_dWh8)[i] = __float2half(dWhh[(g*HH + j)*HH + 8*k8 + c]);
    } else if (idx < EW_F + EWI_F + 2*DW_H) {
        int i = idx - EW_F - EWI_F - DW_H, q = i >> 3, c = i & 7;
        int j = q & 255, g = (q >> 8) % 3, k8 = q / 768;
        ((__half*)g_dWi8)[i] = __float2half(dWih[(g*HH + j)*HH + 8*k8 + c]);
    } else if (idx < PREP_N) {
        int i = idx - EW_F - EWI_F - 2*DW_H;
        int k = i / SS, s = i % SS;
        g_aWh[i] = __float2half(attW[s*AK + k]);
    }
}

// 4-row FMA helper: wv = float4 over 4 consecutive k; hA..hD = float4 of 4 batch rows
// NOTE: macro params must NOT collide with float4 member names (x/y/z/w).
#define ACC4(acc, wv, hA, hB, hC, hD) \
    acc[0] += wv.x*hA.x + wv.y*hB.x + wv.z*hC.x + wv.w*hD.x; \
    acc[1] += wv.x*hA.y + wv.y*hB.y + wv.z*hC.y + wv.w*hD.y; \
    acc[2] += wv.x*hA.z + wv.y*hB.z + wv.z*hC.z + wv.w*hD.z; \
    acc[3] += wv.x*hA.w + wv.y*hB.w + wv.z*hC.w + wv.w*hD.w;

// fp16 8-k FMA helper for decoder GRU (uses h0..h7 from enclosing scope)
#define GACC(acc, uw) { \
    float2 wa = __half22float2(*(__half2*)&uw.x); \
    float2 wb = __half22float2(*(__half2*)&uw.y); \
    float2 wc = __half22float2(*(__half2*)&uw.z); \
    float2 wd = __half22float2(*(__half2*)&uw.w); \
    acc[0] += wa.x*h0.x + wa.y*h1.x + wb.x*h2.x + wb.y*h3.x + wc.x*h4.x + wc.y*h5.x + wd.x*h6.x + wd.y*h7.x; \
    acc[1] += wa.x*h0.y + wa.y*h1.y + wb.x*h2.y + wb.y*h3.y + wc.x*h4.y + wc.y*h5.y + wd.x*h6.y + wd.y*h7.y; \
    acc[2] += wa.x*h0.z + wa.y*h1.z + wb.x*h2.z + wb.y*h3.z + wc.x*h4.z + wc.y*h5.z + wd.x*h6.z + wd.y*h7.z; \
    acc[3] += wa.x*h0.w + wa.y*h1.w + wb.x*h2.w + wb.y*h3.w + wc.x*h4.w + wc.y*h5.w + wd.x*h6.w + wd.y*h7.w; }

// smem layout (bytes):
//   [0, 196608)        enc: cached weights float4[16*768] | dec: attW half[91392] + scores f32[4*336] @182784
//   [196608, 200704)   sh4  float4[256]   hidden state, 4 rows per k
//   [200704, 204800)   sc4  float4[256]   combine
//   [204800, 221184)   sred float[16*256] cross-half reduction
//   [221184, 221440)   syf  float[16*4]   decoder y
//   [221440, 221952)   sxf  float[2*64]   x double buffer
#define SMEM_BYTES 221952

__global__ __launch_bounds__(512, 1) void k_all(
    const float* __restrict__ xb,
    const float* __restrict__ ebih, const float* __restrict__ ebhh,
    const float* __restrict__ attb,
    const float* __restrict__ dbih, const float* __restrict__ dbhh,
    const float* __restrict__ outW, const float* __restrict__ outb,
    const float* __restrict__ linW, const float* __restrict__ linb,
    float* __restrict__ dout)
{
    extern __shared__ char smem[];
    float4* swc  = (float4*)smem;
    __half* aWh  = (__half*)smem;
    float*  ssc  = (float*)(smem + 182784);
    float4* sh4  = (float4*)(smem + 196608);
    float*  shf  = (float*)(smem + 196608);
    float4* sc4  = (float4*)(smem + 200704);
    float*  scf  = (float*)(smem + 200704);
    float*  sred = (float*)(smem + 204800);
    float*  syf  = (float*)(smem + 221184);
    float4* sy4  = (float4*)(smem + 221184);
    float*  sxf  = (float*)(smem + 221440);

    int tx = threadIdx.x;
    int jcol = tx & 255, kh = tx >> 8;
    int lane = tx & 31, warp = tx >> 5;
    int b0 = blockIdx.x * 4;

    // ================= ENCODER =================
    float br  = ebih[jcol]        + ebhh[jcol];
    float bz  = ebih[HH + jcol]   + ebhh[HH + jcol];
    float bnx = ebih[2*HH + jcol];
    float bnh = ebhh[2*HH + jcol];

    // cache 16 of 64 k4-groups in smem (slots: kh0 -> k4g 0..7, kh1 -> k4g 32..39)
    for (int e = tx; e < 16*768; e += 512) {
        int slot = e / 768;
        int k4g = (slot < 8) ? slot : slot + 24;
        swc[e] = g_eW4[k4g*768 + (e % 768)];
    }
    if (tx < 256) sh4[tx] = make_float4(0.f, 0.f, 0.f, 0.f);
    if (tx < 64) {
        int f = tx >> 2, r = tx & 3;
        sxf[f*4 + r] = xb[((b0 + r)*SS + 0)*FF + f];
    }
    __syncthreads();

    for (int s = 0; s < SS; ++s) {
        int cur = s & 1;
        float ar[4] = {0,0,0,0}, az[4] = {0,0,0,0}, am[4] = {0,0,0,0}, ax[4] = {0,0,0,0};

        #pragma unroll
        for (int i = 0; i < 8; ++i) {          // smem-cached weight groups
            int k4g = kh*32 + i;
            const float4* wp = &swc[(kh*8 + i)*768 + jcol];
            float4 wr = wp[0], wz = wp[256], wn = wp[512];
            const float4* hp = &sh4[4*k4g];
            float4 h0 = hp[0], h1 = hp[1], h2 = hp[2], h3 = hp[3];
            ACC4(ar, wr, h0, h1, h2, h3);
            ACC4(az, wz, h0, h1, h2, h3);
            ACC4(am, wn, h0, h1, h2, h3);
        }
        #pragma unroll 4
        for (int i = 8; i < 32; ++i) {         // L2-streamed weight groups
            int k4g = kh*32 + i;
            const float4* wp = &g_eW4[k4g*768 + jcol];
            float4 wr = wp[0], wz = wp[256], wn = wp[512];
            const float4* hp = &sh4[4*k4g];
            float4 h0 = hp[0], h1 = hp[1], h2 = hp[2], h3 = hp[3];
            ACC4(ar, wr, h0, h1, h2, h3);
            ACC4(az, wz, h0, h1, h2, h3);
            ACC4(am, wn, h0, h1, h2, h3);
        }
        if (kh) {                              // Wih * x  (16 k)
            #pragma unroll
            for (int k4 = 0; k4 < 4; ++k4) {
                const float4* wp = &g_eWi4[k4*768 + jcol];
                float4 wr = wp[0], wz = wp[256], wn = wp[512];
                const float4* xp = (const float4*)&sxf[cur*64 + k4*16];
                float4 x0 = xp[0], x1 = xp[1], x2 = xp[2], x3 = xp[3];
                ACC4(ar, wr, x0, x1, x2, x3);
                ACC4(az, wz, x0, x1, x2, x3);
                ACC4(ax, wn, x0, x1, x2, x3);
            }
            #pragma unroll
            for (int i = 0; i < 4; ++i) {
                sred[(i     )*256 + jcol] = ar[i];
                sred[(4  + i)*256 + jcol] = az[i];
                sred[(8  + i)*256 + jcol] = ax[i];
                sred[(12 + i)*256 + jcol] = am[i];
            }
        }
        if (tx < 64 && s + 1 < SS) {           // prefetch next x into other buffer
            int f = tx >> 2, r = tx & 3;
            sxf[(cur ^ 1)*64 + f*4 + r] = xb[((b0 + r)*SS + s + 1)*FF + f];
        }
        __syncthreads();
        if (!kh) {
            float h2v[4];
            #pragma unroll
            for (int i = 0; i < 4; ++i) {
                float arr = ar[i] + sred[(i     )*256 + jcol];
                float azz = az[i] + sred[(4  + i)*256 + jcol];
                float anx =          sred[(8  + i)*256 + jcol];
                float anh = am[i] + sred[(12 + i)*256 + jcol];
                float r = sigf(arr + br);
                float z = sigf(azz + bz);
                float n = tanhf(anx + bnx + r*(anh + bnh));
                float hold = ((const float*)&sh4[jcol])[i];
                h2v[i] = (1.f - z)*n + z*hold;
                g_eoutH[((size_t)(b0 + i)*SS + s)*HH + jcol] = __float2half(h2v[i]);
            }
            sh4[jcol] = make_float4(h2v[0], h2v[1], h2v[2], h2v[3]);
        }
        __syncthreads();
    }

    // ================= DECODER setup =================
    for (int e = tx; e < AW_H/2; e += 512)            // attW fp16 -> smem (overwrites swc)
        ((unsigned int*)aWh)[e] = ((const unsigned int*)g_aWh)[e];
    if (tx < 64) {
        int f = tx >> 2, r = tx & 3;
        syf[f*4 + r] = xb[((b0 + r)*SS + (SS - 1))*FF + f];
    }
    float dbr  = dbih[jcol]        + dbhh[jcol];
    float dbz  = dbih[HH + jcol]   + dbhh[HH + jcol];
    float dbnx = dbih[2*HH + jcol];
    float dbnh = dbhh[2*HH + jcol];
    __syncthreads();

    for (int p = 0; p < PP; ++p) {
        // ---- phase 1: attention scores ----
        if (tx < SS) {
            float bb = attb[tx];
            float ac[4] = {bb, bb, bb, bb};
            #pragma unroll 4
            for (int k = 0; k < HH; ++k) {
                float wsc = __half2float(aWh[k*SS + tx]);
                float4 h4 = sh4[k];
                ac[0] += wsc*h4.x; ac[1] += wsc*h4.y; ac[2] += wsc*h4.z; ac[3] += wsc*h4.w;
            }
            #pragma unroll
            for (int f = 0; f < FF; ++f) {
                float wsc = __half2float(aWh[(HH + f)*SS + tx]);
                float4 y4 = sy4[f];
                ac[0] += wsc*y4.x; ac[1] += wsc*y4.y; ac[2] += wsc*y4.z; ac[3] += wsc*y4.w;
            }
            #pragma unroll
            for (int i = 0; i < 4; ++i) ssc[i*SS + tx] = ac[i];
        }
        __syncthreads();
        // ---- phase 2: softmax (warp w = row w) ----
        if (warp < 4) {
            float mx = -1e30f;
            for (int i = lane; i < SS; i += 32) mx = fmaxf(mx, ssc[warp*SS + i]);
            #pragma unroll
            for (int o = 16; o; o >>= 1) mx = fmaxf(mx, __shfl_xor_sync(0xffffffffu, mx, o));
            float sum = 0.f;
            for (int i = lane; i < SS; i += 32) {
                float e = __expf(ssc[warp*SS + i] - mx);
                ssc[warp*SS + i] = e; sum += e;
            }
            #pragma unroll
            for (int o = 16; o; o >>= 1) sum += __shfl_xor_sync(0xffffffffu, sum, o);
            float inv = 1.f / sum;
            for (int i = lane; i < SS; i += 32) ssc[warp*SS + i] *= inv;
        }
        __syncthreads();
        // ---- phase 3: combine (attn . eout) ----
        {
            int r = tx & 3, colq = (tx >> 2) & 63, lo = tx >> 8;
            const uint2* ep = (const uint2*)(g_eoutH + (size_t)(b0 + r)*SS*HH);
            float a0 = 0, a1 = 0, a2 = 0, a3 = 0;
            int s0 = lo*168;
            #pragma unroll 4
            for (int s2 = s0; s2 < s0 + 168; ++s2) {
                float a = ssc[r*SS + s2];
                uint2 u = ep[s2*64 + colq];
                float2 f01 = __half22float2(*(__half2*)&u.x);
                float2 f23 = __half22float2(*(__half2*)&u.y);
                a0 += a*f01.x; a1 += a*f01.y; a2 += a*f23.x; a3 += a*f23.y;
            }
            if (lo) {
                float* pr = &sred[(tx - 256)*4];
                pr[0] = a0; pr[1] = a1; pr[2] = a2; pr[3] = a3;
            }
            __syncthreads();
            if (!lo) {
                const float* pr = &sred[tx*4];
                a0 += pr[0]; a1 += pr[1]; a2 += pr[2]; a3 += pr[3];
                scf[(colq*4 + 0)*4 + r] = a0;
                scf[(colq*4 + 1)*4 + r] = a1;
                scf[(colq*4 + 2)*4 + r] = a2;
                scf[(colq*4 + 3)*4 + r] = a3;
            }
        }
        __syncthreads();
        // ---- phase 4: decoder GRU (kh0: Whh*h, kh1: Wih*comb; fp16 weights) ----
        {
            const uint4*  Wp  = kh ? g_dWi8 : g_dWh8;
            const float4* inp = kh ? sc4    : sh4;
            float ar[4] = {0,0,0,0}, az[4] = {0,0,0,0}, am[4] = {0,0,0,0};
            #pragma unroll 2
            for (int k8 = 0; k8 < 32; ++k8) {
                const float4* hp = &inp[k8*8];
                float4 h0 = hp[0], h1 = hp[1], h2 = hp[2], h3 = hp[3];
                float4 h4 = hp[4], h5 = hp[5], h6 = hp[6], h7 = hp[7];
                const uint4* wp = &Wp[k8*768 + jcol];
                uint4 uw = wp[0];   GACC(ar, uw);
                uw = wp[256];       GACC(az, uw);
                uw = wp[512];       GACC(am, uw);
            }
            if (kh) {
                #pragma unroll
                for (int i = 0; i < 4; ++i) {
                    sred[(i    )*256 + jcol] = ar[i];
                    sred[(4 + i)*256 + jcol] = az[i];
                    sred[(8 + i)*256 + jcol] = am[i];
                }
            }
            __syncthreads();
            if (!kh) {
                float h2v[4];
                #pragma unroll
                for (int i = 0; i < 4; ++i) {
                    float arr = ar[i] + sred[(i    )*256 + jcol];
                    float azz = az[i] + sred[(4 + i)*256 + jcol];
                    float anx =         sred[(8 + i)*256 + jcol];
                    float anh = am[i];
                    float r = sigf(arr + dbr);
                    float z = sigf(azz + dbz);
                    float n = tanhf(anx + dbnx + r*(anh + dbnh));
                    float hold = ((const float*)&sh4[jcol])[i];
                    h2v[i] = (1.f - z)*n + z*hold;
                }
                sh4[jcol] = make_float4(h2v[0], h2v[1], h2v[2], h2v[3]);
            }
        }
        __syncthreads();
        // ---- phase 5: out projection + final linear (warp w = row w) ----
        if (warp < 4) {
            float fin = 0.f;
            #pragma unroll
            for (int f = 0; f < FF; ++f) {
                float acc = 0.f;
                #pragma unroll
                for (int k = lane; k < HH; k += 32)
                    acc += shf[k*4 + warp] * outW[f*HH + k];
                #pragma unroll
                for (int o = 16; o; o >>= 1) acc += __shfl_xor_sync(0xffffffffu, acc, o);
                if (lane == 0) {
                    float ov = acc + outb[f];
                    syf[f*4 + warp] = ov;
                    fin += ov * linW[f];
                }
            }
            if (lane == 0) dout[(b0 + warp)*PP + p] = fin + linb[0];
        }
        __syncthreads();
    }
}

// ---------------- launch ----------------
extern "C" void kernel_launch(void* const* d_in, const int* in_sizes, int n_in,
                              void* d_out, int out_size)
{
    const float* xb   = (const float*)d_in[0];
    const float* eWih = (const float*)d_in[1];
    const float* eWhh = (const float*)d_in[2];
    const float* ebih = (const float*)d_in[3];
    const float* ebhh = (const float*)d_in[4];
    const float* attW = (const float*)d_in[5];
    const float* attb = (const float*)d_in[6];
    const float* dWih = (const float*)d_in[7];
    const float* dWhh = (const float*)d_in[8];
    const float* dbih = (const float*)d_in[9];
    const float* dbhh = (const float*)d_in[10];
    const float* outW = (const float*)d_in[11];
    const float* outb = (const float*)d_in[12];
    const float* linW = (const float*)d_in[13];
    const float* linb = (const float*)d_in[14];
    float* dout = (float*)d_out;

    cudaFuncSetAttribute(k_all, cudaFuncAttributeMaxDynamicSharedMemorySize, SMEM_BYTES);

    k_prep<<<(PREP_N + 255) / 256, 256>>>(eWih, eWhh, dWih, dWhh, attW);
    k_all<<<BB / 4, 512, SMEM_BYTES>>>(xb, ebih, ebhh, attb, dbih, dbhh,
                                       outW, outb, linW, linb, dout);
}

// round 7
// speedup vs baseline: 4.1392x; 1.1049x over previous
#include <cuda_runtime.h>
#include <cuda_fp16.h>
#include <math.h>

#define BB 512
#define SS 336
#define FF 16
#define HH 256
#define PP 48
#define AK 272   // HH+FF

// ---------------- prepared weights (device globals; allocation-free) ----------------
__device__ uint4  g_eWh8[32*3*256];   // enc Whh fp16: [k8][gate][j], 8 halves/k8 (393 KB)
__device__ uint4  g_eWi8[ 2*3*256];   // enc Wih fp16: [k8][gate][j]              ( 25 KB)
__device__ uint4  g_dWh8[32*3*256];   // dec Whh fp16                             (393 KB)
__device__ uint4  g_dWi8[32*3*256];   // dec Wih fp16                             (393 KB)
__device__ __half g_aWh [AK*SS];      // att_W fp16 transposed [k][s]             (179 KB)
__device__ __half g_eoutH[(size_t)BB*SS*HH]; // encoder outputs fp16 (88 MB, L2-resident)

__device__ __forceinline__ float sigf(float x) { return 1.f / (1.f + __expf(-x)); }

// ---------------- prep: one-time weight transforms ----------------
#define EWH_H (32*3*256*8)
#define EWI_H ( 2*3*256*8)
#define DW_H  (32*3*256*8)
#define AW_H  (AK*SS)
#define PREP_N (EWH_H + EWI_H + 2*DW_H + AW_H)

__global__ void k_prep(const float* __restrict__ eWih, const float* __restrict__ eWhh,
                       const float* __restrict__ dWih, const float* __restrict__ dWhh,
                       const float* __restrict__ attW)
{
    int idx = blockIdx.x * 256 + threadIdx.x;
    if (idx < EWH_H) {
        int c = idx & 7, q = idx >> 3;
        int j = q & 255, g = (q >> 8) % 3, k8 = q / 768;
        ((__half*)g_eWh8)[idx] = __float2half(eWhh[(g*HH + j)*HH + 8*k8 + c]);
    } else if (idx < EWH_H + EWI_H) {
        int i = idx - EWH_H, c = i & 7, q = i >> 3;
        int j = q & 255, g = (q >> 8) % 3, k8 = q / 768;
        ((__half*)g_eWi8)[i] = __float2half(eWih[(g*HH + j)*FF + 8*k8 + c]);
    } else if (idx < EWH_H + EWI_H + DW_H) {
        int i = idx - EWH_H - EWI_H, c = i & 7, q = i >> 3;
        int j = q & 255, g = (q >> 8) % 3, k8 = q / 768;
        ((__half*)g_dWh8)[i] = __float2half(dWhh[(g*HH + j)*HH + 8*k8 + c]);
    } else if (idx < EWH_H + EWI_H + 2*DW_H) {
        int i = idx - EWH_H - EWI_H - DW_H, c = i & 7, q = i >> 3;
        int j = q & 255, g = (q >> 8) % 3, k8 = q / 768;
        ((__half*)g_dWi8)[i] = __float2half(dWih[(g*HH + j)*HH + 8*k8 + c]);
    } else if (idx < PREP_N) {
        int i = idx - EWH_H - EWI_H - 2*DW_H;
        int k = i / SS, s = i % SS;
        g_aWh[i] = __float2half(attW[s*AK + k]);
    }
}

// ---------------- packed f32x2 helpers (sm_10x FFMA2) ----------------
#define FMA2(acc, wa, hb) \
    asm("fma.rn.f32x2 %0, %1, %2, %3;" : "=l"(acc) : "l"(wa), "l"(hb), "l"(acc))
#define PACK2(wd, fv) { unsigned int u_ = __float_as_uint(fv); \
    asm("mov.b64 %0, {%1, %1};" : "=l"(wd) : "r"(u_)); }
#define UNPK(d0, d1, v) { unsigned int u0_, u1_; \
    asm("mov.b64 {%0, %1}, %2;" : "=r"(u0_), "=r"(u1_) : "l"(v)); \
    d0 = __uint_as_float(u0_); d1 = __uint_as_float(u1_); }

// 8-k fp16-weight packed FMA: uses hp0..hp7 (ulonglong2: .x=rows01, .y=rows23) from scope
#define W8FMA(a01, a23, uw) { \
    float2 wf_; unsigned long long wd_; \
    wf_ = __half22float2(*(const __half2*)&(uw).x); \
    PACK2(wd_, wf_.x); FMA2(a01, wd_, hp0.x); FMA2(a23, wd_, hp0.y); \
    PACK2(wd_, wf_.y); FMA2(a01, wd_, hp1.x); FMA2(a23, wd_, hp1.y); \
    wf_ = __half22float2(*(const __half2*)&(uw).y); \
    PACK2(wd_, wf_.x); FMA2(a01, wd_, hp2.x); FMA2(a23, wd_, hp2.y); \
    PACK2(wd_, wf_.y); FMA2(a01, wd_, hp3.x); FMA2(a23, wd_, hp3.y); \
    wf_ = __half22float2(*(const __half2*)&(uw).z); \
    PACK2(wd_, wf_.x); FMA2(a01, wd_, hp4.x); FMA2(a23, wd_, hp4.y); \
    PACK2(wd_, wf_.y); FMA2(a01, wd_, hp5.x); FMA2(a23, wd_, hp5.y); \
    wf_ = __half22float2(*(const __half2*)&(uw).w); \
    PACK2(wd_, wf_.x); FMA2(a01, wd_, hp6.x); FMA2(a23, wd_, hp6.y); \
    PACK2(wd_, wf_.y); FMA2(a01, wd_, hp7.x); FMA2(a23, wd_, hp7.y); }

#define LOADH(hb) \
    ulonglong2 hp0 = hb[0], hp1 = hb[1], hp2 = hb[2], hp3 = hb[3], \
               hp4 = hb[4], hp5 = hb[5], hp6 = hb[6], hp7 = hb[7];

// smem layout (bytes):
//   [0, 196608)        enc: cached fp16 weights uint4[16*768] | dec: attW half + scores f32 @182784
//   [196608, 200704)   sh4  float4[256]   hidden state (4 rows per k)
//   [200704, 204800)   sc4  float4[256]   combine
//   [204800, 221184)   sred float[16*256] cross-half reduction
//   [221184, 221440)   syf  float[16*4]   decoder y
//   [221440, 221952)   sxf  float[2*64]   x double buffer
#define SMEM_BYTES 221952

__global__ __launch_bounds__(512, 1) void k_all(
    const float* __restrict__ xb,
    const float* __restrict__ ebih, const float* __restrict__ ebhh,
    const float* __restrict__ attb,
    const float* __restrict__ dbih, const float* __restrict__ dbhh,
    const float* __restrict__ outW, const float* __restrict__ outb,
    const float* __restrict__ linW, const float* __restrict__ linb,
    float* __restrict__ dout)
{
    extern __shared__ char smem[];
    uint4*  swc4 = (uint4*)smem;
    __half* aWh  = (__half*)smem;
    float*  ssc  = (float*)(smem + 182784);
    float4* sh4  = (float4*)(smem + 196608);
    float*  shf  = (float*)(smem + 196608);
    float4* sc4  = (float4*)(smem + 200704);
    float*  scf  = (float*)(smem + 200704);
    float*  sred = (float*)(smem + 204800);
    float*  syf  = (float*)(smem + 221184);
    float4* sy4  = (float4*)(smem + 221184);
    float*  sxf  = (float*)(smem + 221440);

    int tx = threadIdx.x;
    int jcol = tx & 255, kh = tx >> 8;
    int lane = tx & 31, warp = tx >> 5;
    int b0 = blockIdx.x * 4;

    // ================= ENCODER =================
    float br  = ebih[jcol]        + ebhh[jcol];
    float bz  = ebih[HH + jcol]   + ebhh[HH + jcol];
    float bnx = ebih[2*HH + jcol];
    float bnh = ebhh[2*HH + jcol];

    // cache 16 of 32 k8-groups (kh0: k8 0..7, kh1: k8 16..23) = 192 KB
    for (int e = tx; e < 16*768; e += 512) {
        int slot = e / 768;
        int k8src = (slot < 8) ? slot : slot + 8;
        swc4[e] = g_eWh8[k8src*768 + (e % 768)];
    }
    if (tx < 256) sh4[tx] = make_float4(0.f, 0.f, 0.f, 0.f);
    if (tx < 64) {
        int f = tx >> 2, r = tx & 3;
        sxf[f*4 + r] = xb[((b0 + r)*SS + 0)*FF + f];
    }
    __syncthreads();

    for (int s = 0; s < SS; ++s) {
        int cur = s & 1;
        unsigned long long ar01 = 0, ar23 = 0, az01 = 0, az23 = 0;
        unsigned long long am01 = 0, am23 = 0, ax01 = 0, ax23 = 0;

        #pragma unroll 2
        for (int i = 0; i < 8; ++i) {          // smem-cached weight groups
            int k8 = kh*16 + i;
            const ulonglong2* hb = (const ulonglong2*)&sh4[k8*8];
            LOADH(hb);
            const uint4* wp = &swc4[(kh*8 + i)*768 + jcol];
            uint4 uw = wp[0];   W8FMA(ar01, ar23, uw);
            uw = wp[256];       W8FMA(az01, az23, uw);
            uw = wp[512];       W8FMA(am01, am23, uw);
        }
        #pragma unroll 4
        for (int i = 8; i < 16; ++i) {         // L2-streamed weight groups
            int k8 = kh*16 + i;
            const ulonglong2* hb = (const ulonglong2*)&sh4[k8*8];
            LOADH(hb);
            const uint4* wp = &g_eWh8[k8*768 + jcol];
            uint4 uw = wp[0];   W8FMA(ar01, ar23, uw);
            uw = wp[256];       W8FMA(az01, az23, uw);
            uw = wp[512];       W8FMA(am01, am23, uw);
        }
        if (kh) {                              // Wih * x (16 k = 2 k8-groups)
            #pragma unroll
            for (int g8 = 0; g8 < 2; ++g8) {
                const ulonglong2* hb = (const ulonglong2*)&sxf[cur*64 + g8*32];
                LOADH(hb);
                const uint4* wp = &g_eWi8[g8*768 + jcol];
                uint4 uw = wp[0];   W8FMA(ar01, ar23, uw);
                uw = wp[256];       W8FMA(az01, az23, uw);
                uw = wp[512];       W8FMA(ax01, ax23, uw);
            }
            float arv[4], azv[4], axv[4], amv[4];
            UNPK(arv[0], arv[1], ar01); UNPK(arv[2], arv[3], ar23);
            UNPK(azv[0], azv[1], az01); UNPK(azv[2], azv[3], az23);
            UNPK(axv[0], axv[1], ax01); UNPK(axv[2], axv[3], ax23);
            UNPK(amv[0], amv[1], am01); UNPK(amv[2], amv[3], am23);
            #pragma unroll
            for (int i = 0; i < 4; ++i) {
                sred[(i     )*256 + jcol] = arv[i];
                sred[(4  + i)*256 + jcol] = azv[i];
                sred[(8  + i)*256 + jcol] = axv[i];
                sred[(12 + i)*256 + jcol] = amv[i];
            }
        }
        if (tx < 64 && s + 1 < SS) {           // prefetch next x
            int f = tx >> 2, r = tx & 3;
            sxf[(cur ^ 1)*64 + f*4 + r] = xb[((b0 + r)*SS + s + 1)*FF + f];
        }
        __syncthreads();
        if (!kh) {
            float arv[4], azv[4], amv[4];
            UNPK(arv[0], arv[1], ar01); UNPK(arv[2], arv[3], ar23);
            UNPK(azv[0], azv[1], az01); UNPK(azv[2], azv[3], az23);
            UNPK(amv[0], amv[1], am01); UNPK(amv[2], amv[3], am23);
            float h2v[4];
            #pragma unroll
            for (int i = 0; i < 4; ++i) {
                float arr = arv[i] + sred[(i     )*256 + jcol];
                float azz = azv[i] + sred[(4  + i)*256 + jcol];
                float anx =          sred[(8  + i)*256 + jcol];
                float anh = amv[i] + sred[(12 + i)*256 + jcol];
                float r = sigf(arr + br);
                float z = sigf(azz + bz);
                float n = tanhf(anx + bnx + r*(anh + bnh));
                float hold = ((const float*)&sh4[jcol])[i];
                h2v[i] = (1.f - z)*n + z*hold;
                g_eoutH[((size_t)(b0 + i)*SS + s)*HH + jcol] = __float2half(h2v[i]);
            }
            sh4[jcol] = make_float4(h2v[0], h2v[1], h2v[2], h2v[3]);
        }
        __syncthreads();
    }

    // ================= DECODER setup =================
    for (int e = tx; e < AW_H/2; e += 512)            // attW fp16 -> smem (overwrites swc)
        ((unsigned int*)aWh)[e] = ((const unsigned int*)g_aWh)[e];
    if (tx < 64) {
        int f = tx >> 2, r = tx & 3;
        syf[f*4 + r] = xb[((b0 + r)*SS + (SS - 1))*FF + f];
    }
    float dbr  = dbih[jcol]        + dbhh[jcol];
    float dbz  = dbih[HH + jcol]   + dbhh[HH + jcol];
    float dbnx = dbih[2*HH + jcol];
    float dbnh = dbhh[2*HH + jcol];
    __syncthreads();

    for (int p = 0; p < PP; ++p) {
        // ---- phase 1: attention scores ----
        if (tx < SS) {
            float bb = attb[tx];
            float ac[4] = {bb, bb, bb, bb};
            #pragma unroll 4
            for (int k = 0; k < HH; ++k) {
                float wsc = __half2float(aWh[k*SS + tx]);
                float4 h4 = sh4[k];
                ac[0] += wsc*h4.x; ac[1] += wsc*h4.y; ac[2] += wsc*h4.z; ac[3] += wsc*h4.w;
            }
            #pragma unroll
            for (int f = 0; f < FF; ++f) {
                float wsc = __half2float(aWh[(HH + f)*SS + tx]);
                float4 y4 = sy4[f];
                ac[0] += wsc*y4.x; ac[1] += wsc*y4.y; ac[2] += wsc*y4.z; ac[3] += wsc*y4.w;
            }
            #pragma unroll
            for (int i = 0; i < 4; ++i) ssc[i*SS + tx] = ac[i];
        }
        __syncthreads();
        // ---- phase 2: softmax (warp w = row w) ----
        if (warp < 4) {
            float mx = -1e30f;
            for (int i = lane; i < SS; i += 32) mx = fmaxf(mx, ssc[warp*SS + i]);
            #pragma unroll
            for (int o = 16; o; o >>= 1) mx = fmaxf(mx, __shfl_xor_sync(0xffffffffu, mx, o));
            float sum = 0.f;
            for (int i = lane; i < SS; i += 32) {
                float e = __expf(ssc[warp*SS + i] - mx);
                ssc[warp*SS + i] = e; sum += e;
            }
            #pragma unroll
            for (int o = 16; o; o >>= 1) sum += __shfl_xor_sync(0xffffffffu, sum, o);
            float inv = 1.f / sum;
            for (int i = lane; i < SS; i += 32) ssc[warp*SS + i] *= inv;
        }
        __syncthreads();
        // ---- phase 3: combine (attn . eout) ----
        {
            int r = tx & 3, colq = (tx >> 2) & 63, lo = tx >> 8;
            const uint2* ep = (const uint2*)(g_eoutH + (size_t)(b0 + r)*SS*HH);
            float a0 = 0, a1 = 0, a2 = 0, a3 = 0;
            int s0 = lo*168;
            #pragma unroll 4
            for (int s2 = s0; s2 < s0 + 168; ++s2) {
                float a = ssc[r*SS + s2];
                uint2 u = ep[s2*64 + colq];
                float2 f01 = __half22float2(*(__half2*)&u.x);
                float2 f23 = __half22float2(*(__half2*)&u.y);
                a0 += a*f01.x; a1 += a*f01.y; a2 += a*f23.x; a3 += a*f23.y;
            }
            if (lo) {
                float* pr = &sred[(tx - 256)*4];
                pr[0] = a0; pr[1] = a1; pr[2] = a2; pr[3] = a3;
            }
            __syncthreads();
            if (!lo) {
                const float* pr = &sred[tx*4];
                a0 += pr[0]; a1 += pr[1]; a2 += pr[2]; a3 += pr[3];
                scf[(colq*4 + 0)*4 + r] = a0;
                scf[(colq*4 + 1)*4 + r] = a1;
                scf[(colq*4 + 2)*4 + r] = a2;
                scf[(colq*4 + 3)*4 + r] = a3;
            }
        }
        __syncthreads();
        // ---- phase 4: decoder GRU (kh0: Whh*h, kh1: Wih*comb; packed f32x2) ----
        {
            const uint4*  Wp  = kh ? g_dWi8 : g_dWh8;
            const float4* inp = kh ? sc4    : sh4;
            unsigned long long ar01 = 0, ar23 = 0, az01 = 0, az23 = 0, am01 = 0, am23 = 0;
            #pragma unroll 2
            for (int k8 = 0; k8 < 32; ++k8) {
                const ulonglong2* hb = (const ulonglong2*)&inp[k8*8];
                LOADH(hb);
                const uint4* wp = &Wp[k8*768 + jcol];
                uint4 uw = wp[0];   W8FMA(ar01, ar23, uw);
                uw = wp[256];       W8FMA(az01, az23, uw);
                uw = wp[512];       W8FMA(am01, am23, uw);
            }
            float arv[4], azv[4], amv[4];
            UNPK(arv[0], arv[1], ar01); UNPK(arv[2], arv[3], ar23);
            UNPK(azv[0], azv[1], az01); UNPK(azv[2], azv[3], az23);
            UNPK(amv[0], amv[1], am01); UNPK(amv[2], amv[3], am23);
            if (kh) {
                #pragma unroll
                for (int i = 0; i < 4; ++i) {
                    sred[(i    )*256 + jcol] = arv[i];
                    sred[(4 + i)*256 + jcol] = azv[i];
                    sred[(8 + i)*256 + jcol] = amv[i];
                }
            }
            __syncthreads();
            if (!kh) {
                float h2v[4];
                #pragma unroll
                for (int i = 0; i < 4; ++i) {
                    float arr = arv[i] + sred[(i    )*256 + jcol];
                    float azz = azv[i] + sred[(4 + i)*256 + jcol];
                    float anx =          sred[(8 + i)*256 + jcol];
                    float anh = amv[i];
                    float r = sigf(arr + dbr);
                    float z = sigf(azz + dbz);
                    float n = tanhf(anx + dbnx + r*(anh + dbnh));
                    float hold = ((const float*)&sh4[jcol])[i];
                    h2v[i] = (1.f - z)*n + z*hold;
                }
                sh4[jcol] = make_float4(h2v[0], h2v[1], h2v[2], h2v[3]);
            }
        }
        __syncthreads();
        // ---- phase 5: out projection + final linear (warp w = row w) ----
        if (warp < 4) {
            float fin = 0.f;
            #pragma unroll
            for (int f = 0; f < FF; ++f) {
                float acc = 0.f;
                #pragma unroll
                for (int k = lane; k < HH; k += 32)
                    acc += shf[k*4 + warp] * outW[f*HH + k];
                #pragma unroll
                for (int o = 16; o; o >>= 1) acc += __shfl_xor_sync(0xffffffffu, acc, o);
                if (lane == 0) {
                    float ov = acc + outb[f];
                    syf[f*4 + warp] = ov;
                    fin += ov * linW[f];
                }
            }
            if (lane == 0) dout[(b0 + warp)*PP + p] = fin + linb[0];
        }
        __syncthreads();
    }
}

// ---------------- launch ----------------
extern "C" void kernel_launch(void* const* d_in, const int* in_sizes, int n_in,
                              void* d_out, int out_size)
{
    const float* xb   = (const float*)d_in[0];
    const float* eWih = (const float*)d_in[1];
    const float* eWhh = (const float*)d_in[2];
    const float* ebih = (const float*)d_in[3];
    const float* ebhh = (const float*)d_in[4];
    const float* attW = (const float*)d_in[5];
    const float* attb = (const float*)d_in[6];
    const float* dWih = (const float*)d_in[7];
    const float* dWhh = (const float*)d_in[8];
    const float* dbih = (const float*)d_in[9];
    const float* dbhh = (const float*)d_in[10];
    const float* outW = (const float*)d_in[11];
    const float* outb = (const float*)d_in[12];
    const float* linW = (const float*)d_in[13];
    const float* linb = (const float*)d_in[14];
    float* dout = (float*)d_out;

    cudaFuncSetAttribute(k_all, cudaFuncAttributeMaxDynamicSharedMemorySize, SMEM_BYTES);

    k_prep<<<(PREP_N + 255) / 256, 256>>>(eWih, eWhh, dWih, dWhh, attW);
    k_all<<<BB / 4, 512, SMEM_BYTES>>>(xb, ebih, ebhh, attb, dbih, dbhh,
                                       outW, outb, linW, linb, dout);
}

// round 8
// speedup vs baseline: 4.2777x; 1.0335x over previous
#include <cuda_runtime.h>
#include <cuda_fp16.h>
#include <math.h>

#define BB 512
#define SS 336
#define FF 16
#define HH 256
#define PP 48
#define AK 272   // HH+FF

// ---------------- prepared weights (device globals; allocation-free) ----------------
__device__ uint4  g_eWh8[32*3*256];   // enc Whh fp16: [k8][gate][j], 8 halves/k8 (393 KB)
__device__ uint4  g_eWi8[ 2*3*256];   // enc Wih fp16: [k8][gate][j]              ( 25 KB)
__device__ uint4  g_dWh8[32*3*256];   // dec Whh fp16                             (393 KB)
__device__ uint4  g_dWi8[32*3*256];   // dec Wih fp16                             (393 KB)
__device__ __half g_aWh [AK*SS];      // att_W fp16 transposed [k][s]             (179 KB)
__device__ __half g_eoutH[(size_t)BB*SS*HH]; // encoder outputs fp16 (88 MB, L2-resident)

__device__ __forceinline__ float sigf(float x) { return 1.f / (1.f + __expf(-x)); }

// ---------------- prep: one-time weight transforms ----------------
#define EWH_H (32*3*256*8)
#define EWI_H ( 2*3*256*8)
#define DW_H  (32*3*256*8)
#define AW_H  (AK*SS)
#define PREP_N (EWH_H + EWI_H + 2*DW_H + AW_H)

__global__ void k_prep(const float* __restrict__ eWih, const float* __restrict__ eWhh,
                       const float* __restrict__ dWih, const float* __restrict__ dWhh,
                       const float* __restrict__ attW)
{
    int idx = blockIdx.x * 256 + threadIdx.x;
    if (idx < EWH_H) {
        int c = idx & 7, q = idx >> 3;
        int j = q & 255, g = (q >> 8) % 3, k8 = q / 768;
        ((__half*)g_eWh8)[idx] = __float2half(eWhh[(g*HH + j)*HH + 8*k8 + c]);
    } else if (idx < EWH_H + EWI_H) {
        int i = idx - EWH_H, c = i & 7, q = i >> 3;
        int j = q & 255, g = (q >> 8) % 3, k8 = q / 768;
        ((__half*)g_eWi8)[i] = __float2half(eWih[(g*HH + j)*FF + 8*k8 + c]);
    } else if (idx < EWH_H + EWI_H + DW_H) {
        int i = idx - EWH_H - EWI_H, c = i & 7, q = i >> 3;
        int j = q & 255, g = (q >> 8) % 3, k8 = q / 768;
        ((__half*)g_dWh8)[i] = __float2half(dWhh[(g*HH + j)*HH + 8*k8 + c]);
    } else if (idx < EWH_H + EWI_H + 2*DW_H) {
        int i = idx - EWH_H - EWI_H - DW_H, c = i & 7, q = i >> 3;
        int j = q & 255, g = (q >> 8) % 3, k8 = q / 768;
        ((__half*)g_dWi8)[i] = __float2half(dWih[(g*HH + j)*HH + 8*k8 + c]);
    } else if (idx < PREP_N) {
        int i = idx - EWH_H - EWI_H - 2*DW_H;
        int k = i / SS, s = i % SS;
        g_aWh[i] = __float2half(attW[s*AK + k]);
    }
}

// ---------------- packed f32x2 helpers ----------------
#define FMA2(acc, wa, hb) \
    asm("fma.rn.f32x2 %0, %1, %2, %3;" : "=l"(acc) : "l"(wa), "l"(hb), "l"(acc))
#define PACK2(wd, fv) { unsigned int u_ = __float_as_uint(fv); \
    asm("mov.b64 %0, {%1, %1};" : "=l"(wd) : "r"(u_)); }
#define UNPK(d0, d1, v) { unsigned int u0_, u1_; \
    asm("mov.b64 {%0, %1}, %2;" : "=r"(u0_), "=r"(u1_) : "l"(v)); \
    d0 = __uint_as_float(u0_); d1 = __uint_as_float(u1_); }

// 2-k fp16-weight packed FMA: comp = uint holding halves (k, k+1); hA/hB = rows01|rows23 at k, k+1
#define W2FMA(aLo, aHi, comp, hA, hB) { \
    float2 wf_ = __half22float2(*(const __half2*)&(comp)); \
    unsigned long long wd_; \
    PACK2(wd_, wf_.x); FMA2(aLo, wd_, (hA).x); FMA2(aHi, wd_, (hA).y); \
    PACK2(wd_, wf_.y); FMA2(aLo, wd_, (hB).x); FMA2(aHi, wd_, (hB).y); }

// one k8 group (8 k) for 3 gates, h loaded in two k4 sub-chunks (16 regs live, not 32)
#define K8GRP(aR0,aR1,aZ0,aZ1,aN0,aN1, wR,wZ,wN, hbase) { \
    { ulonglong2 hA=(hbase)[0], hB=(hbase)[1], hC=(hbase)[2], hD=(hbase)[3]; \
      W2FMA(aR0,aR1,(wR).x,hA,hB); W2FMA(aR0,aR1,(wR).y,hC,hD); \
      W2FMA(aZ0,aZ1,(wZ).x,hA,hB); W2FMA(aZ0,aZ1,(wZ).y,hC,hD); \
      W2FMA(aN0,aN1,(wN).x,hA,hB); W2FMA(aN0,aN1,(wN).y,hC,hD); } \
    { ulonglong2 hA=(hbase)[4], hB=(hbase)[5], hC=(hbase)[6], hD=(hbase)[7]; \
      W2FMA(aR0,aR1,(wR).z,hA,hB); W2FMA(aR0,aR1,(wR).w,hC,hD); \
      W2FMA(aZ0,aZ1,(wZ).z,hA,hB); W2FMA(aZ0,aZ1,(wZ).w,hC,hD); \
      W2FMA(aN0,aN1,(wN).z,hA,hB); W2FMA(aN0,aN1,(wN).w,hC,hD); } }

// smem layout (bytes):
//   [0, 196608)        enc: cached fp16 weights uint4[16*768] | dec: attW half + scores f32 @182784
//   [196608, 200704)   sh4  float4[256]   hidden state (4 rows per k)
//   [200704, 204800)   sc4  float4[256]   combine
//   [204800, 221184)   sred float[16*256] cross-half reduction
//   [221184, 221440)   syf  float[16*4]   decoder y
//   [221440, 221952)   sxf  float[2*64]   x double buffer
#define SMEM_BYTES 221952

__global__ __launch_bounds__(512, 1) void k_all(
    const float* __restrict__ xb,
    const float* __restrict__ ebih, const float* __restrict__ ebhh,
    const float* __restrict__ attb,
    const float* __restrict__ dbih, const float* __restrict__ dbhh,
    const float* __restrict__ outW, const float* __restrict__ outb,
    const float* __restrict__ linW, const float* __restrict__ linb,
    float* __restrict__ dout)
{
    extern __shared__ char smem[];
    uint4*  swc4 = (uint4*)smem;
    __half* aWh  = (__half*)smem;
    float*  ssc  = (float*)(smem + 182784);
    float4* sh4  = (float4*)(smem + 196608);
    float*  shf  = (float*)(smem + 196608);
    float4* sc4  = (float4*)(smem + 200704);
    float*  scf  = (float*)(smem + 200704);
    float*  sred = (float*)(smem + 204800);
    float*  syf  = (float*)(smem + 221184);
    float4* sy4  = (float4*)(smem + 221184);
    float*  sxf  = (float*)(smem + 221440);

    int tx = threadIdx.x;
    int jcol = tx & 255, kh = tx >> 8;
    int lane = tx & 31, warp = tx >> 5;
    int b0 = blockIdx.x * 4;

    // ================= ENCODER =================
    float br  = ebih[jcol]        + ebhh[jcol];
    float bz  = ebih[HH + jcol]   + ebhh[HH + jcol];
    float bnx = ebih[2*HH + jcol];
    float bnh = ebhh[2*HH + jcol];

    // cache 16 of 32 k8-groups (kh0: k8 0..7, kh1: k8 16..23) = 192 KB
    for (int e = tx; e < 16*768; e += 512) {
        int slot = e / 768;
        int k8src = (slot < 8) ? slot : slot + 8;
        swc4[e] = g_eWh8[k8src*768 + (e % 768)];
    }
    if (tx < 256) sh4[tx] = make_float4(0.f, 0.f, 0.f, 0.f);
    if (tx < 64) {
        int f = tx >> 2, r = tx & 3;
        sxf[f*4 + r] = xb[((b0 + r)*SS + 0)*FF + f];
    }
    __syncthreads();

    for (int s = 0; s < SS; ++s) {
        int cur = s & 1;
        unsigned long long ar01=0,ar23=0,az01=0,az23=0,am01=0,am23=0,ax01=0,ax23=0;

        #pragma unroll 2
        for (int i = 0; i < 8; ++i) {          // smem-cached weight groups
            const uint4* wp = &swc4[(kh*8 + i)*768 + jcol];
            uint4 cwr = wp[0], cwz = wp[256], cwn = wp[512];
            const ulonglong2* hb = (const ulonglong2*)&sh4[(kh*16 + i)*8];
            K8GRP(ar01,ar23,az01,az23,am01,am23, cwr,cwz,cwn, hb);
        }
        {                                       // L2-streamed groups, depth-1 prefetch
            const uint4* sp = &g_eWh8[(kh*16 + 8)*768 + jcol];
            uint4 cwr = sp[0], cwz = sp[256], cwn = sp[512];
            #pragma unroll
            for (int i = 8; i < 16; ++i) {
                uint4 nwr = cwr, nwz = cwz, nwn = cwn;
                if (i < 15) {
                    const uint4* np = &g_eWh8[(kh*16 + i + 1)*768 + jcol];
                    nwr = np[0]; nwz = np[256]; nwn = np[512];
                }
                const ulonglong2* hb = (const ulonglong2*)&sh4[(kh*16 + i)*8];
                K8GRP(ar01,ar23,az01,az23,am01,am23, cwr,cwz,cwn, hb);
                cwr = nwr; cwz = nwz; cwn = nwn;
            }
        }
        if (kh) {                               // Wih * x (2 k8 groups), n-part into ax
            #pragma unroll
            for (int g8 = 0; g8 < 2; ++g8) {
                const uint4* wp = &g_eWi8[g8*768 + jcol];
                uint4 cwr = wp[0], cwz = wp[256], cwn = wp[512];
                const ulonglong2* hb = (const ulonglong2*)&sxf[cur*64 + g8*32];
                K8GRP(ar01,ar23,az01,az23,ax01,ax23, cwr,cwz,cwn, hb);
            }
        }
        float arv[4], azv[4], amv[4], axv[4];
        UNPK(arv[0], arv[1], ar01); UNPK(arv[2], arv[3], ar23);
        UNPK(azv[0], azv[1], az01); UNPK(azv[2], azv[3], az23);
        UNPK(amv[0], amv[1], am01); UNPK(amv[2], amv[3], am23);
        UNPK(axv[0], axv[1], ax01); UNPK(axv[2], axv[3], ax23);

        if (kh) {   // store rows 0,1 partials (incl. all x-parts)
            sred[0*256 + jcol] = arv[0]; sred[1*256 + jcol] = arv[1];
            sred[2*256 + jcol] = azv[0]; sred[3*256 + jcol] = azv[1];
            sred[4*256 + jcol] = axv[0]; sred[5*256 + jcol] = axv[1];
            sred[6*256 + jcol] = amv[0]; sred[7*256 + jcol] = amv[1];
        } else {    // store rows 2,3 partials (h-parts only)
            sred[ 8*256 + jcol] = arv[2]; sred[ 9*256 + jcol] = arv[3];
            sred[10*256 + jcol] = azv[2]; sred[11*256 + jcol] = azv[3];
            sred[12*256 + jcol] = amv[2]; sred[13*256 + jcol] = amv[3];
        }
        if (tx < 64 && s + 1 < SS) {            // prefetch next x
            int f = tx >> 2, r = tx & 3;
            sxf[(cur ^ 1)*64 + f*4 + r] = xb[((b0 + r)*SS + s + 1)*FF + f];
        }
        __syncthreads();
        if (!kh) {  // finalize rows 0,1
            #pragma unroll
            for (int i = 0; i < 2; ++i) {
                float arr = arv[i] + sred[(0 + i)*256 + jcol];
                float azz = azv[i] + sred[(2 + i)*256 + jcol];
                float anx =          sred[(4 + i)*256 + jcol];
                float anh = amv[i] + sred[(6 + i)*256 + jcol];
                float r = sigf(arr + br);
                float z = sigf(azz + bz);
                float n = tanhf(anx + bnx + r*(anh + bnh));
                float hold = shf[jcol*4 + i];
                float h2 = (1.f - z)*n + z*hold;
                shf[jcol*4 + i] = h2;
                g_eoutH[((size_t)(b0 + i)*SS + s)*HH + jcol] = __float2half(h2);
            }
        } else {    // finalize rows 2,3
            #pragma unroll
            for (int i = 2; i < 4; ++i) {
                float arr = arv[i] + sred[( 8 + i - 2)*256 + jcol];
                float azz = azv[i] + sred[(10 + i - 2)*256 + jcol];
                float anx = axv[i];
                float anh = amv[i] + sred[(12 + i - 2)*256 + jcol];
                float r = sigf(arr + br);
                float z = sigf(azz + bz);
                float n = tanhf(anx + bnx + r*(anh + bnh));
                float hold = shf[jcol*4 + i];
                float h2 = (1.f - z)*n + z*hold;
                shf[jcol*4 + i] = h2;
                g_eoutH[((size_t)(b0 + i)*SS + s)*HH + jcol] = __float2half(h2);
            }
        }
        __syncthreads();
    }

    // ================= DECODER setup =================
    for (int e = tx; e < AW_H/2; e += 512)            // attW fp16 -> smem (overwrites swc)
        ((unsigned int*)aWh)[e] = ((const unsigned int*)g_aWh)[e];
    if (tx < 64) {
        int f = tx >> 2, r = tx & 3;
        syf[f*4 + r] = xb[((b0 + r)*SS + (SS - 1))*FF + f];
    }
    float dbr  = dbih[jcol]        + dbhh[jcol];
    float dbz  = dbih[HH + jcol]   + dbhh[HH + jcol];
    float dbnx = dbih[2*HH + jcol];
    float dbnh = dbhh[2*HH + jcol];
    __syncthreads();

    for (int p = 0; p < PP; ++p) {
        // ---- phase 1: attention scores ----
        if (tx < SS) {
            float bb = attb[tx];
            float ac[4] = {bb, bb, bb, bb};
            #pragma unroll 4
            for (int k = 0; k < HH; ++k) {
                float wsc = __half2float(aWh[k*SS + tx]);
                float4 h4 = sh4[k];
                ac[0] += wsc*h4.x; ac[1] += wsc*h4.y; ac[2] += wsc*h4.z; ac[3] += wsc*h4.w;
            }
            #pragma unroll
            for (int f = 0; f < FF; ++f) {
                float wsc = __half2float(aWh[(HH + f)*SS + tx]);
                float4 y4 = sy4[f];
                ac[0] += wsc*y4.x; ac[1] += wsc*y4.y; ac[2] += wsc*y4.z; ac[3] += wsc*y4.w;
            }
            #pragma unroll
            for (int i = 0; i < 4; ++i) ssc[i*SS + tx] = ac[i];
        }
        __syncthreads();
        // ---- phase 2: softmax (warp w = row w) ----
        if (warp < 4) {
            float mx = -1e30f;
            for (int i = lane; i < SS; i += 32) mx = fmaxf(mx, ssc[warp*SS + i]);
            #pragma unroll
            for (int o = 16; o; o >>= 1) mx = fmaxf(mx, __shfl_xor_sync(0xffffffffu, mx, o));
            float sum = 0.f;
            for (int i = lane; i < SS; i += 32) {
                float e = __expf(ssc[warp*SS + i] - mx);
                ssc[warp*SS + i] = e; sum += e;
            }
            #pragma unroll
            for (int o = 16; o; o >>= 1) sum += __shfl_xor_sync(0xffffffffu, sum, o);
            float inv = 1.f / sum;
            for (int i = lane; i < SS; i += 32) ssc[warp*SS + i] *= inv;
        }
        __syncthreads();
        // ---- phase 3: combine (attn . eout) ----
        {
            int r = tx & 3, colq = (tx >> 2) & 63, lo = tx >> 8;
            const uint2* ep = (const uint2*)(g_eoutH + (size_t)(b0 + r)*SS*HH);
            float a0 = 0, a1 = 0, a2 = 0, a3 = 0;
            int s0 = lo*168;
            #pragma unroll 4
            for (int s2 = s0; s2 < s0 + 168; ++s2) {
                float a = ssc[r*SS + s2];
                uint2 u = ep[s2*64 + colq];
                float2 f01 = __half22float2(*(__half2*)&u.x);
                float2 f23 = __half22float2(*(__half2*)&u.y);
                a0 += a*f01.x; a1 += a*f01.y; a2 += a*f23.x; a3 += a*f23.y;
            }
            if (lo) {
                float* pr = &sred[(tx - 256)*4];
                pr[0] = a0; pr[1] = a1; pr[2] = a2; pr[3] = a3;
            }
            __syncthreads();
            if (!lo) {
                const float* pr = &sred[tx*4];
                a0 += pr[0]; a1 += pr[1]; a2 += pr[2]; a3 += pr[3];
                scf[(colq*4 + 0)*4 + r] = a0;
                scf[(colq*4 + 1)*4 + r] = a1;
                scf[(colq*4 + 2)*4 + r] = a2;
                scf[(colq*4 + 3)*4 + r] = a3;
            }
        }
        __syncthreads();
        // ---- phase 4: decoder GRU (kh0: Whh*h, kh1: Wih*comb; prefetch pipeline) ----
        {
            const uint4*  basep = kh ? g_dWi8 : g_dWh8;
            const float4* inp   = kh ? sc4    : sh4;
            unsigned long long ar01=0,ar23=0,az01=0,az23=0,am01=0,am23=0;
            uint4 cwr = basep[jcol], cwz = basep[256 + jcol], cwn = basep[512 + jcol];
            #pragma unroll 4
            for (int k8 = 0; k8 < 32; ++k8) {
                uint4 nwr = cwr, nwz = cwz, nwn = cwn;
                if (k8 < 31) {
                    const uint4* np = &basep[(k8 + 1)*768 + jcol];
                    nwr = np[0]; nwz = np[256]; nwn = np[512];
                }
                const ulonglong2* hb = (const ulonglong2*)&inp[k8*8];
                K8GRP(ar01,ar23,az01,az23,am01,am23, cwr,cwz,cwn, hb);
                cwr = nwr; cwz = nwz; cwn = nwn;
            }
            float arv[4], azv[4], amv[4];
            UNPK(arv[0], arv[1], ar01); UNPK(arv[2], arv[3], ar23);
            UNPK(azv[0], azv[1], az01); UNPK(azv[2], azv[3], az23);
            UNPK(amv[0], amv[1], am01); UNPK(amv[2], amv[3], am23);
            if (kh) {   // Wih*comb side: rows 0,1 (am = nx here)
                sred[0*256 + jcol] = arv[0]; sred[1*256 + jcol] = arv[1];
                sred[2*256 + jcol] = azv[0]; sred[3*256 + jcol] = azv[1];
                sred[4*256 + jcol] = amv[0]; sred[5*256 + jcol] = amv[1];
            } else {    // Whh*h side: rows 2,3 (am = nh here)
                sred[ 6*256 + jcol] = arv[2]; sred[ 7*256 + jcol] = arv[3];
                sred[ 8*256 + jcol] = azv[2]; sred[ 9*256 + jcol] = azv[3];
                sred[10*256 + jcol] = amv[2]; sred[11*256 + jcol] = amv[3];
            }
            __syncthreads();
            if (!kh) {  // finalize rows 0,1: own = h-side, sred = x-side
                #pragma unroll
                for (int i = 0; i < 2; ++i) {
                    float arr = arv[i] + sred[(0 + i)*256 + jcol];
                    float azz = azv[i] + sred[(2 + i)*256 + jcol];
                    float anx = sred[(4 + i)*256 + jcol];
                    float anh = amv[i];
                    float r = sigf(arr + dbr);
                    float z = sigf(azz + dbz);
                    float n = tanhf(anx + dbnx + r*(anh + dbnh));
                    float hold = shf[jcol*4 + i];
                    shf[jcol*4 + i] = (1.f - z)*n + z*hold;
                }
            } else {    // finalize rows 2,3: own = x-side, sred = h-side
                #pragma unroll
                for (int i = 2; i < 4; ++i) {
                    float arr = arv[i] + sred[( 6 + i - 2)*256 + jcol];
                    float azz = azv[i] + sred[( 8 + i - 2)*256 + jcol];
                    float anx = amv[i];
                    float anh = sred[(10 + i - 2)*256 + jcol];
                    float r = sigf(arr + dbr);
                    float z = sigf(azz + dbz);
                    float n = tanhf(anx + dbnx + r*(anh + dbnh));
                    float hold = shf[jcol*4 + i];
                    shf[jcol*4 + i] = (1.f - z)*n + z*hold;
                }
            }
        }
        __syncthreads();
        // ---- phase 5: out projection + final linear (warp w = row w) ----
        if (warp < 4) {
            float fin = 0.f;
            #pragma unroll
            for (int f = 0; f < FF; ++f) {
                float acc = 0.f;
                #pragma unroll
                for (int k = lane; k < HH; k += 32)
                    acc += shf[k*4 + warp] * outW[f*HH + k];
                #pragma unroll
                for (int o = 16; o; o >>= 1) acc += __shfl_xor_sync(0xffffffffu, acc, o);
                if (lane == 0) {
                    float ov = acc + outb[f];
                    syf[f*4 + warp] = ov;
                    fin += ov * linW[f];
                }
            }
            if (lane == 0) dout[(b0 + warp)*PP + p] = fin + linb[0];
        }
        __syncthreads();
    }
}

// ---------------- launch ----------------
extern "C" void kernel_launch(void* const* d_in, const int* in_sizes, int n_in,
                              void* d_out, int out_size)
{
    const float* xb   = (const float*)d_in[0];
    const float* eWih = (const float*)d_in[1];
    const float* eWhh = (const float*)d_in[2];
    const float* ebih = (const float*)d_in[3];
    const float* ebhh = (const float*)d_in[4];
    const float* attW = (const float*)d_in[5];
    const float* attb = (const float*)d_in[6];
    const float* dWih = (const float*)d_in[7];
    const float* dWhh = (const float*)d_in[8];
    const float* dbih = (const float*)d_in[9];
    const float* dbhh = (const float*)d_in[10];
    const float* outW = (const float*)d_in[11];
    const float* outb = (const float*)d_in[12];
    const float* linW = (const float*)d_in[13];
    const float* linb = (const float*)d_in[14];
    float* dout = (float*)d_out;

    cudaFuncSetAttribute(k_all, cudaFuncAttributeMaxDynamicSharedMemorySize, SMEM_BYTES);

    k_prep<<<(PREP_N + 255) / 256, 256>>>(eWih, eWhh, dWih, dWhh, attW);
    k_all<<<BB / 4, 512, SMEM_BYTES>>>(xb, ebih, ebhh, attb, dbih, dbhh,
                                       outW, outb, linW, linb, dout);
}

// round 9
// speedup vs baseline: 5.2460x; 1.2264x over previous
#include <cuda_runtime.h>
#include <cuda_fp16.h>
#include <math.h>

#define BB 512
#define SS 336
#define FF 16
#define HH 256
#define PP 48
#define AK 272   // HH+FF

// ---------------- fragment-major prepared weights (device globals) ----------------
// A-fragment for mma.m16n8k16 tile (mt, kt), lane l:
//   rows m_lo = 16*mt + l/4, m_hi = m_lo+8; cols c0 = 16*kt + 2*(l%4)
//   uint4 = { h2(W[m_lo][c0],W[m_lo][c0+1]), h2(W[m_hi][c0],W[m_hi][c0+1]),
//             h2(W[m_lo][c0+8],W[m_lo][c0+9]), h2(W[m_hi][c0+8],W[m_hi][c0+9]) }
__device__ uint4 g_encWfrag[16*48*32];   // enc Whh  (393 KB)
__device__ uint4 g_encIfrag[   48*32];   // enc Wih  (24 KB, single ktile K=16)
__device__ uint4 g_decWfrag[32*48*32];   // dec [Whh | Wih] kt<16 / kt>=16 (786 KB)
__device__ uint4 g_attfrag [17*21*32];   // att_W 336x272 (183 KB)
__device__ __half g_eoutH[(size_t)BB*SS*HH]; // encoder outputs fp16 (88 MB)

__device__ __forceinline__ float sigf(float x) { return 1.f / (1.f + __expf(-x)); }
__device__ __forceinline__ unsigned int pk2(float a, float b) {
    __half2 h = __floats2half2_rn(a, b);
    return *reinterpret_cast<unsigned int*>(&h);
}

// ---------------- prep: build all fragments ----------------
#define N_ENCW (16*48*32)
#define N_ENCI (48*32)
#define N_DECW (32*48*32)
#define N_ATT  (17*21*32)
#define PREP_N (N_ENCW + N_ENCI + N_DECW + N_ATT)

__global__ void k_prep(const float* __restrict__ eWih, const float* __restrict__ eWhh,
                       const float* __restrict__ dWih, const float* __restrict__ dWhh,
                       const float* __restrict__ attW)
{
    int idx = blockIdx.x * 256 + threadIdx.x;
    if (idx >= PREP_N) return;
    const float* src; uint4* dst; int mt, l, c0, ldk;
    if (idx < N_ENCW) {
        int kt = idx / 1536, r = idx % 1536; mt = r / 32; l = r % 32;
        c0 = kt*16 + (l & 3)*2; src = eWhh; ldk = HH; dst = &g_encWfrag[idx];
    } else if (idx < N_ENCW + N_ENCI) {
        int i = idx - N_ENCW; mt = i / 32; l = i % 32;
        c0 = (l & 3)*2; src = eWih; ldk = FF; dst = &g_encIfrag[i];
    } else if (idx < N_ENCW + N_ENCI + N_DECW) {
        int i = idx - N_ENCW - N_ENCI;
        int kt = i / 1536, r = i % 1536; mt = r / 32; l = r % 32;
        if (kt < 16) { src = dWhh; c0 = kt*16 + (l & 3)*2; }
        else         { src = dWih; c0 = (kt - 16)*16 + (l & 3)*2; }
        ldk = HH; dst = &g_decWfrag[i];
    } else {
        int i = idx - N_ENCW - N_ENCI - N_DECW;
        int kt = i / 672, r = i % 672; mt = r / 32; l = r % 32;
        c0 = kt*16 + (l & 3)*2; src = attW; ldk = AK; dst = &g_attfrag[i];
    }
    int mlo = mt*16 + (l >> 2), mhi = mlo + 8;
    uint4 o;
    o.x = pk2(src[mlo*ldk + c0],     src[mlo*ldk + c0 + 1]);
    o.y = pk2(src[mhi*ldk + c0],     src[mhi*ldk + c0 + 1]);
    o.z = pk2(src[mlo*ldk + c0 + 8], src[mlo*ldk + c0 + 9]);
    o.w = pk2(src[mhi*ldk + c0 + 8], src[mhi*ldk + c0 + 9]);
    *dst = o;
}

// ---------------- mma wrapper ----------------
#define MMA(d, a, bb0, bb1) \
    asm volatile("mma.sync.aligned.m16n8k16.row.col.f32.f16.f16.f32 " \
        "{%0,%1,%2,%3}, {%4,%5,%6,%7}, {%8,%9}, {%0,%1,%2,%3};" \
        : "+f"(d[0]), "+f"(d[1]), "+f"(d[2]), "+f"(d[3]) \
        : "r"((a).x), "r"((a).y), "r"((a).z), "r"((a).w), "r"(bb0), "r"(bb1))

// B fragment from fp16 table tb (row stride RS halves): lane n=l/4 row, k0 = 16kt+2*(l%4)
#define BFRAG(bb0, bb1, tb, RS, kbase) { \
    const __half* tp_ = (tb) + (l >> 2)*(RS) + (kbase) + (l & 3)*2; \
    bb0 = *(const unsigned int*)tp_; \
    bb1 = *(const unsigned int*)(tp_ + 8); }

// smem layout (bytes)
#define OFF_WC  0         // uint4[7*48*32] weight cache          172032
#define OFF_PL  172032    // f32 planes [4][256][8] / scores      32768
#define OFF_HF  204800    // f32 h-state [256][8]                 8192
#define OFF_HT  212992    // fp16 table [8][304]  (h | x/y)       4864
#define OFF_CT  217856    // fp16 comb  [8][280]                  4480
#define OFF_BI  222336    // f32 biases [4][256]                  4096
#define OFF_AB  226432    // f32 attb [336]                       1344
#define SMEM_BYTES 227776
#define HT_RS 304
#define CT_RS 280

__global__ __launch_bounds__(512, 1) void k_all(
    const float* __restrict__ xb,
    const float* __restrict__ ebih, const float* __restrict__ ebhh,
    const float* __restrict__ attb,
    const float* __restrict__ dbih, const float* __restrict__ dbhh,
    const float* __restrict__ outW, const float* __restrict__ outb,
    const float* __restrict__ linW, const float* __restrict__ linb,
    float* __restrict__ dout)
{
    extern __shared__ char smx[];
    uint4*  wc = (uint4*)(smx + OFF_WC);
    float*  PL = (float*)(smx + OFF_PL);
    float*  hF = (float*)(smx + OFF_HF);
    __half* hT = (__half*)(smx + OFF_HT);
    __half* cT = (__half*)(smx + OFF_CT);
    float*  BI = (float*)(smx + OFF_BI);
    float*  AB = (float*)(smx + OFF_AB);

    int tx = threadIdx.x, l = tx & 31, w = tx >> 5;
    int b0 = blockIdx.x * 8;
    int mt0 = w * 3;

    // ---- init: cache enc weights (kt0-5 + Wih in slot 6), biases, zero state ----
    for (int e = tx; e < 7*1536; e += 512)
        wc[e] = (e < 6*1536) ? g_encWfrag[e] : g_encIfrag[e - 6*1536];
    if (tx < 256) {
        BI[tx]       = ebih[tx]        + ebhh[tx];
        BI[256 + tx] = ebih[HH + tx]   + ebhh[HH + tx];
        BI[512 + tx] = ebih[2*HH + tx];
        BI[768 + tx] = ebhh[2*HH + tx];
    }
    for (int e = tx; e < 256*8; e += 512) hF[e] = 0.f;
    for (int e = tx; e < 8*HT_RS; e += 512) hT[e] = __float2half(0.f);
    __syncthreads();
    if (tx < 128) { int b = tx >> 4, f = tx & 15;
        hT[b*HT_RS + 256 + f] = __float2half(xb[((b0 + b)*SS + 0)*FF + f]); }
    __syncthreads();

    // ================= ENCODER =================
    for (int s = 0; s < SS; ++s) {
        float accA[3][4] = {}, accB[3][4] = {};
        unsigned int bb0, bb1;
        #pragma unroll
        for (int kt = 0; kt < 6; ++kt) {          // cached ktiles
            BFRAG(bb0, bb1, hT, HT_RS, kt*16);
            #pragma unroll
            for (int i = 0; i < 3; ++i) {
                uint4 a = wc[(kt*48 + mt0 + i)*32 + l];
                MMA(accA[i], a, bb0, bb1);
            }
        }
        {                                          // streamed kt 6..15 (prefetch-1)
            uint4 pf[3];
            #pragma unroll
            for (int i = 0; i < 3; ++i) pf[i] = g_encWfrag[(6*48 + mt0 + i)*32 + l];
            #pragma unroll 1
            for (int kt = 6; kt < 16; ++kt) {
                uint4 cu[3];
                #pragma unroll
                for (int i = 0; i < 3; ++i) cu[i] = pf[i];
                if (kt < 15) {
                    #pragma unroll
                    for (int i = 0; i < 3; ++i)
                        pf[i] = g_encWfrag[((kt + 1)*48 + mt0 + i)*32 + l];
                }
                BFRAG(bb0, bb1, hT, HT_RS, kt*16);
                #pragma unroll
                for (int i = 0; i < 3; ++i) MMA(accA[i], cu[i], bb0, bb1);
            }
        }
        {                                          // x tile (cached slot 6, k=256..271)
            BFRAG(bb0, bb1, hT, HT_RS, 256);
            #pragma unroll
            for (int i = 0; i < 3; ++i) {
                uint4 a = wc[(6*48 + mt0 + i)*32 + l];
                MMA(accB[i], a, bb0, bb1);
            }
        }
        // store to gate planes: r,z summed; n split into nh(accA)/nx(accB)
        #pragma unroll
        for (int i = 0; i < 3; ++i) {
            int mt = mt0 + i, g = mt >> 4;
            int jr = (mt & 15)*16 + (l >> 2), cb = (l & 3)*2;
            if (g < 2) {
                *(float2*)&PL[(g*256 + jr)*8 + cb]     = make_float2(accA[i][0]+accB[i][0], accA[i][1]+accB[i][1]);
                *(float2*)&PL[(g*256 + jr + 8)*8 + cb] = make_float2(accA[i][2]+accB[i][2], accA[i][3]+accB[i][3]);
            } else {
                *(float2*)&PL[(2*256 + jr)*8 + cb]     = make_float2(accA[i][0], accA[i][1]);
                *(float2*)&PL[(2*256 + jr + 8)*8 + cb] = make_float2(accA[i][2], accA[i][3]);
                *(float2*)&PL[(3*256 + jr)*8 + cb]     = make_float2(accB[i][0], accB[i][1]);
                *(float2*)&PL[(3*256 + jr + 8)*8 + cb] = make_float2(accB[i][2], accB[i][3]);
            }
        }
        __syncthreads();
        // GRU update: thread -> (j, 4 batch rows)
        {
            int j = tx & 255, hq = tx >> 8;
            #pragma unroll
            for (int q = 0; q < 4; ++q) {
                int b = hq*4 + q;
                float r = sigf(PL[j*8 + b] + BI[j]);
                float z = sigf(PL[2048 + j*8 + b] + BI[256 + j]);
                float n = tanhf(PL[6144 + j*8 + b] + BI[512 + j]
                              + r*(PL[4096 + j*8 + b] + BI[768 + j]));
                float hold = hF[j*8 + b];
                float h2 = (1.f - z)*n + z*hold;
                hF[j*8 + b] = h2;
                hT[b*HT_RS + j] = __float2half(h2);
                g_eoutH[((size_t)(b0 + b)*SS + s)*HH + j] = __float2half(h2);
            }
            if (tx < 128 && s + 1 < SS) { int b = tx >> 4, f = tx & 15;
                hT[b*HT_RS + 256 + f] = __float2half(xb[((b0 + b)*SS + s + 1)*FF + f]); }
        }
        __syncthreads();
    }

    // ================= DECODER setup =================
    for (int e = tx; e < 7*1536; e += 512) wc[e] = g_decWfrag[e];
    if (tx < 256) {
        BI[tx]       = dbih[tx]        + dbhh[tx];
        BI[256 + tx] = dbih[HH + tx]   + dbhh[HH + tx];
        BI[512 + tx] = dbih[2*HH + tx];
        BI[768 + tx] = dbhh[2*HH + tx];
    }
    if (tx < 128) { int b = tx >> 4, f = tx & 15;
        hT[b*HT_RS + 256 + f] = __float2half(xb[((b0 + b)*SS + (SS - 1))*FF + f]); }
    for (int e = tx; e < SS; e += 512) AB[e] = attb[e];
    __syncthreads();

    for (int p = 0; p < PP; ++p) {
        // ---- phase A: attention scores via mma (A = attfrag streamed) ----
        {
            int nmt = (w < 5) ? 2 : 1;
            float acc[2][4] = {};
            unsigned int bb0, bb1;
            #pragma unroll 1
            for (int kt = 0; kt < 17; ++kt) {
                BFRAG(bb0, bb1, hT, HT_RS, kt*16);
                #pragma unroll
                for (int i = 0; i < 2; ++i) if (i < nmt) {
                    uint4 a = g_attfrag[(kt*21 + (w + i*16))*32 + l];
                    MMA(acc[i], a, bb0, bb1);
                }
            }
            #pragma unroll
            for (int i = 0; i < 2; ++i) if (i < nmt) {
                int sr = (w + i*16)*16 + (l >> 2), cb = (l & 3)*2;
                *(float2*)&PL[sr*8 + cb]       = make_float2(acc[i][0] + AB[sr], acc[i][1] + AB[sr]);
                *(float2*)&PL[(sr + 8)*8 + cb] = make_float2(acc[i][2] + AB[sr + 8], acc[i][3] + AB[sr + 8]);
            }
        }
        __syncthreads();
        // ---- phase B: softmax (warp w = batch row) ----
        if (w < 8) {
            float mx = -1e30f;
            for (int i = l; i < SS; i += 32) mx = fmaxf(mx, PL[i*8 + w]);
            #pragma unroll
            for (int o = 16; o; o >>= 1) mx = fmaxf(mx, __shfl_xor_sync(0xffffffffu, mx, o));
            float sum = 0.f;
            for (int i = l; i < SS; i += 32) {
                float e = __expf(PL[i*8 + w] - mx);
                PL[i*8 + w] = e; sum += e;
            }
            #pragma unroll
            for (int o = 16; o; o >>= 1) sum += __shfl_xor_sync(0xffffffffu, sum, o);
            float inv = 1.f / sum;
            for (int i = l; i < SS; i += 32) PL[i*8 + w] *= inv;
        }
        __syncthreads();
        // ---- phase C: combine -> cT fp16 ----
        {
            int b = tx >> 6, cq = tx & 63;
            const uint2* ep = (const uint2*)(g_eoutH + (size_t)(b0 + b)*SS*HH) + cq;
            float c0 = 0, c1 = 0, c2 = 0, c3 = 0;
            #pragma unroll 4
            for (int s2 = 0; s2 < SS; ++s2) {
                float a = PL[s2*8 + b];
                uint2 u = ep[s2*64];
                float2 f01 = __half22float2(*(__half2*)&u.x);
                float2 f23 = __half22float2(*(__half2*)&u.y);
                c0 += a*f01.x; c1 += a*f01.y; c2 += a*f23.x; c3 += a*f23.y;
            }
            __half2* cp = (__half2*)(cT + b*CT_RS);
            cp[cq*2]     = __floats2half2_rn(c0, c1);
            cp[cq*2 + 1] = __floats2half2_rn(c2, c3);
        }
        __syncthreads();
        // ---- phase D: decoder GRU mma (kt<16: Whh x h -> accA; kt>=16: Wih x comb -> accB) ----
        {
            float accA[3][4] = {}, accB[3][4] = {};
            unsigned int bb0, bb1;
            #pragma unroll
            for (int kt = 0; kt < 7; ++kt) {       // cached
                BFRAG(bb0, bb1, hT, HT_RS, kt*16);
                #pragma unroll
                for (int i = 0; i < 3; ++i) {
                    uint4 a = wc[(kt*48 + mt0 + i)*32 + l];
                    MMA(accA[i], a, bb0, bb1);
                }
            }
            {                                       // streamed kt 7..15 (h side)
                uint4 pf[3];
                #pragma unroll
                for (int i = 0; i < 3; ++i) pf[i] = g_decWfrag[(7*48 + mt0 + i)*32 + l];
                #pragma unroll 1
                for (int kt = 7; kt < 16; ++kt) {
                    uint4 cu[3];
                    #pragma unroll
                    for (int i = 0; i < 3; ++i) cu[i] = pf[i];
                    #pragma unroll
                    for (int i = 0; i < 3; ++i)
                        pf[i] = g_decWfrag[((kt + 1)*48 + mt0 + i)*32 + l];
                    BFRAG(bb0, bb1, hT, HT_RS, kt*16);
                    #pragma unroll
                    for (int i = 0; i < 3; ++i) MMA(accA[i], cu[i], bb0, bb1);
                }
                #pragma unroll 1
                for (int kt = 16; kt < 32; ++kt) {  // streamed (comb side)
                    uint4 cu[3];
                    #pragma unroll
                    for (int i = 0; i < 3; ++i) cu[i] = pf[i];
                    if (kt < 31) {
                        #pragma unroll
                        for (int i = 0; i < 3; ++i)
                            pf[i] = g_decWfrag[((kt + 1)*48 + mt0 + i)*32 + l];
                    }
                    BFRAG(bb0, bb1, cT, CT_RS, (kt - 16)*16);
                    #pragma unroll
                    for (int i = 0; i < 3; ++i) MMA(accB[i], cu[i], bb0, bb1);
                }
            }
            #pragma unroll
            for (int i = 0; i < 3; ++i) {
                int mt = mt0 + i, g = mt >> 4;
                int jr = (mt & 15)*16 + (l >> 2), cb = (l & 3)*2;
                if (g < 2) {
                    *(float2*)&PL[(g*256 + jr)*8 + cb]     = make_float2(accA[i][0]+accB[i][0], accA[i][1]+accB[i][1]);
                    *(float2*)&PL[(g*256 + jr + 8)*8 + cb] = make_float2(accA[i][2]+accB[i][2], accA[i][3]+accB[i][3]);
                } else {
                    *(float2*)&PL[(2*256 + jr)*8 + cb]     = make_float2(accA[i][0], accA[i][1]);
                    *(float2*)&PL[(2*256 + jr + 8)*8 + cb] = make_float2(accA[i][2], accA[i][3]);
                    *(float2*)&PL[(3*256 + jr)*8 + cb]     = make_float2(accB[i][0], accB[i][1]);
                    *(float2*)&PL[(3*256 + jr + 8)*8 + cb] = make_float2(accB[i][2], accB[i][3]);
                }
            }
        }
        __syncthreads();
        // GRU update
        {
            int j = tx & 255, hq = tx >> 8;
            #pragma unroll
            for (int q = 0; q < 4; ++q) {
                int b = hq*4 + q;
                float r = sigf(PL[j*8 + b] + BI[j]);
                float z = sigf(PL[2048 + j*8 + b] + BI[256 + j]);
                float n = tanhf(PL[6144 + j*8 + b] + BI[512 + j]
                              + r*(PL[4096 + j*8 + b] + BI[768 + j]));
                float hold = hF[j*8 + b];
                float h2 = (1.f - z)*n + z*hold;
                hF[j*8 + b] = h2;
                hT[b*HT_RS + j] = __float2half(h2);
            }
        }
        __syncthreads();
        // ---- phase E: out projection + final linear (warp = batch row) ----
        if (w < 8) {
            float fin = 0.f;
            #pragma unroll
            for (int f = 0; f < FF; ++f) {
                float acc = 0.f;
                #pragma unroll
                for (int k = l; k < HH; k += 32) acc += hF[k*8 + w] * outW[f*HH + k];
                #pragma unroll
                for (int o = 16; o; o >>= 1) acc += __shfl_xor_sync(0xffffffffu, acc, o);
                if (l == 0) {
                    float ov = acc + outb[f];
                    hT[w*HT_RS + 256 + f] = __float2half(ov);
                    fin += ov * linW[f];
                }
            }
            if (l == 0) dout[(b0 + w)*PP + p] = fin + linb[0];
        }
        __syncthreads();
    }
}

// ---------------- launch ----------------
extern "C" void kernel_launch(void* const* d_in, const int* in_sizes, int n_in,
                              void* d_out, int out_size)
{
    const float* xb   = (const float*)d_in[0];
    const float* eWih = (const float*)d_in[1];
    const float* eWhh = (const float*)d_in[2];
    const float* ebih = (const float*)d_in[3];
    const float* ebhh = (const float*)d_in[4];
    const float* attW = (const float*)d_in[5];
    const float* attb = (const float*)d_in[6];
    const float* dWih = (const float*)d_in[7];
    const float* dWhh = (const float*)d_in[8];
    const float* dbih = (const float*)d_in[9];
    const float* dbhh = (const float*)d_in[10];
    const float* outW = (const float*)d_in[11];
    const float* outb = (const float*)d_in[12];
    const float* linW = (const float*)d_in[13];
    const float* linb = (const float*)d_in[14];
    float* dout = (float*)d_out;

    cudaFuncSetAttribute(k_all, cudaFuncAttributeMaxDynamicSharedMemorySize, SMEM_BYTES);

    k_prep<<<(PREP_N + 255) / 256, 256>>>(eWih, eWhh, dWih, dWhh, attW);
    k_all<<<BB / 8, 512, SMEM_BYTES>>>(xb, ebih, ebhh, attb, dbih, dbhh,
                                       outW, outb, linW, linb, dout);
}

// round 10
// speedup vs baseline: 7.8302x; 1.4926x over previous
#include <cuda_runtime.h>
#include <cuda_fp16.h>
#include <math.h>

#define BB 512
#define SS 336
#define FF 16
#define HH 256
#define PP 48
#define AK 272   // HH+FF

// ---------------- fragment-major prepared weights (device globals) ----------------
__device__ uint4 g_encWfrag[16*48*32];   // enc Whh  (393 KB)
__device__ uint4 g_encIfrag[   48*32];   // enc Wih  (24 KB, single ktile K=16)
__device__ uint4 g_decWfrag[32*48*32];   // dec [Whh | Wih] kt<16 / kt>=16 (786 KB)
__device__ uint4 g_attfrag [17*21*32];   // att_W 336x272 (183 KB)
__device__ __half g_eoutH[(size_t)BB*SS*HH]; // encoder outputs fp16 (88 MB)

__device__ __forceinline__ float sigf(float x) { return 1.f / (1.f + __expf(-x)); }
__device__ __forceinline__ unsigned int pk2(float a, float b) {
    __half2 h = __floats2half2_rn(a, b);
    return *reinterpret_cast<unsigned int*>(&h);
}

// ---------------- prep: build all fragments (unchanged layouts) ----------------
#define N_ENCW (16*48*32)
#define N_ENCI (48*32)
#define N_DECW (32*48*32)
#define N_ATT  (17*21*32)
#define PREP_N (N_ENCW + N_ENCI + N_DECW + N_ATT)

__global__ void k_prep(const float* __restrict__ eWih, const float* __restrict__ eWhh,
                       const float* __restrict__ dWih, const float* __restrict__ dWhh,
                       const float* __restrict__ attW)
{
    int idx = blockIdx.x * 256 + threadIdx.x;
    if (idx >= PREP_N) return;
    const float* src; uint4* dst; int mt, l, c0, ldk;
    if (idx < N_ENCW) {
        int kt = idx / 1536, r = idx % 1536; mt = r / 32; l = r % 32;
        c0 = kt*16 + (l & 3)*2; src = eWhh; ldk = HH; dst = &g_encWfrag[idx];
    } else if (idx < N_ENCW + N_ENCI) {
        int i = idx - N_ENCW; mt = i / 32; l = i % 32;
        c0 = (l & 3)*2; src = eWih; ldk = FF; dst = &g_encIfrag[i];
    } else if (idx < N_ENCW + N_ENCI + N_DECW) {
        int i = idx - N_ENCW - N_ENCI;
        int kt = i / 1536, r = i % 1536; mt = r / 32; l = r % 32;
        if (kt < 16) { src = dWhh; c0 = kt*16 + (l & 3)*2; }
        else         { src = dWih; c0 = (kt - 16)*16 + (l & 3)*2; }
        ldk = HH; dst = &g_decWfrag[i];
    } else {
        int i = idx - N_ENCW - N_ENCI - N_DECW;
        int kt = i / 672, r = i % 672; mt = r / 32; l = r % 32;
        c0 = kt*16 + (l & 3)*2; src = attW; ldk = AK; dst = &g_attfrag[i];
    }
    int mlo = mt*16 + (l >> 2), mhi = mlo + 8;
    uint4 o;
    o.x = pk2(src[mlo*ldk + c0],     src[mlo*ldk + c0 + 1]);
    o.y = pk2(src[mhi*ldk + c0],     src[mhi*ldk + c0 + 1]);
    o.z = pk2(src[mlo*ldk + c0 + 8], src[mlo*ldk + c0 + 9]);
    o.w = pk2(src[mhi*ldk + c0 + 8], src[mhi*ldk + c0 + 9]);
    *dst = o;
}

// ---------------- mma / cluster helpers ----------------
#define MMA(d, a, bb0, bb1) \
    asm volatile("mma.sync.aligned.m16n8k16.row.col.f32.f16.f16.f32 " \
        "{%0,%1,%2,%3}, {%4,%5,%6,%7}, {%8,%9}, {%0,%1,%2,%3};" \
        : "+f"(d[0]), "+f"(d[1]), "+f"(d[2]), "+f"(d[3]) \
        : "r"((a).x), "r"((a).y), "r"((a).z), "r"((a).w), "r"(bb0), "r"(bb1))

#define BFRAG(bb0, bb1, tb, RS, kbase) { \
    const __half* tp_ = (tb) + (l >> 2)*(RS) + (kbase) + (l & 3)*2; \
    bb0 = *(const unsigned int*)tp_; \
    bb1 = *(const unsigned int*)(tp_ + 8); }

__device__ __forceinline__ unsigned int smem_u32(const void* p) {
    unsigned int a;
    asm("{ .reg .u64 t; cvta.to.shared.u64 t, %1; cvt.u32.u64 %0, t; }" : "=r"(a) : "l"(p));
    return a;
}
__device__ __forceinline__ unsigned int mapa32(unsigned int a, unsigned int r) {
    unsigned int o; asm("mapa.shared::cluster.u32 %0, %1, %2;" : "=r"(o) : "r"(a), "r"(r)); return o;
}
__device__ __forceinline__ void stc16(unsigned int a, unsigned short v) {
    asm volatile("st.shared::cluster.u16 [%0], %1;" :: "r"(a), "h"(v));
}
__device__ __forceinline__ void stc32(unsigned int a, unsigned int v) {
    asm volatile("st.shared::cluster.u32 [%0], %1;" :: "r"(a), "r"(v));
}
#define CLUSTER_SYNC() do { \
    asm volatile("barrier.cluster.arrive.aligned;" ::: "memory"); \
    asm volatile("barrier.cluster.wait.aligned;"   ::: "memory"); } while (0)

// smem layout (bytes)
#define WC_SLOTS 14
#define OFF_WC 0                          // 14*24*32*16 = 172032
#define OFF_PL 172032                     // planes (stride-10) / scores / scratch: 20480
#define OFF_HF 192512                     // f32 own-j hold [128][10]: 5120
#define OFF_HT 197632                     // fp16 h tables, 2 bufs x 8x312: 9984
#define OFF_CT 207616                     // fp16 comb [8][280]: 4480
#define OFF_BI 212096                     // f32 own-j biases [4][128]: 2048
#define OFF_AB 214144                     // f32 attb [336]: 1344
#define SMEM_BYTES 215552
#define HT_RS 312
#define CT_RS 280

__global__ __launch_bounds__(512, 1) __cluster_dims__(2, 1, 1)
void k_all(
    const float* __restrict__ xb,
    const float* __restrict__ ebih, const float* __restrict__ ebhh,
    const float* __restrict__ attb,
    const float* __restrict__ dbih, const float* __restrict__ dbhh,
    const float* __restrict__ outW, const float* __restrict__ outb,
    const float* __restrict__ linW, const float* __restrict__ linb,
    float* __restrict__ dout)
{
    extern __shared__ char smx[];
    uint4*  wc   = (uint4*)(smx + OFF_WC);
    float*  PL   = (float*)(smx + OFF_PL);
    float*  SCR  = (float*)(smx + OFF_PL + 12288);
    float*  hF   = (float*)(smx + OFF_HF);
    __half* hTb0 = (__half*)(smx + OFF_HT);
    __half* hTb1 = (__half*)(smx + OFF_HT + 4992);
    __half* cT   = (__half*)(smx + OFF_CT);
    float*  BI   = (float*)(smx + OFF_BI);
    float*  AB   = (float*)(smx + OFF_AB);

    int tx = threadIdx.x, l = tx & 31, w = tx >> 5;
    unsigned int rank; asm("mov.u32 %0, %%cluster_ctarank;" : "=r"(rank));
    int b0 = (blockIdx.x >> 1) * 8;
    int jbase = (int)rank << 7;
    bool hv = (w < 8);
    int m1 = w, m2 = 16 + w;
    int mtg1 = (m1 >> 3)*16 + (int)rank*8 + (m1 & 7);
    int mtg2 = 32 + (int)rank*8 + (m2 & 7);

    unsigned int peerHT0 = mapa32(smem_u32(hTb0), rank ^ 1u);
    unsigned int peerHT1 = mapa32(smem_u32(hTb1), rank ^ 1u);
    unsigned int peerCT  = mapa32(smem_u32(cT),  rank ^ 1u);

    // ---- init: encoder weight cache (kt 0..12 + x slot 13), biases, state ----
    for (int e = tx; e < WC_SLOTS*768; e += 512) {
        int slot = e / 768, m = (e % 768) >> 5, ll = e & 31;
        int mtg = (m >> 3)*16 + (int)rank*8 + (m & 7);
        if (slot < 13)       wc[e] = g_encWfrag[(slot*48 + mtg)*32 + ll];
        else if (slot == 13) wc[e] = g_encIfrag[mtg*32 + ll];
    }
    if (tx < 128) {
        BI[tx]       = ebih[jbase + tx]        + ebhh[jbase + tx];
        BI[128 + tx] = ebih[HH + jbase + tx]   + ebhh[HH + jbase + tx];
        BI[256 + tx] = ebih[2*HH + jbase + tx];
        BI[384 + tx] = ebhh[2*HH + jbase + tx];
    }
    for (int e = tx; e < 1280; e += 512) hF[e] = 0.f;
    for (int e = tx; e < 8*HT_RS; e += 512) hTb0[e] = __float2half(0.f);
    __syncthreads();
    if (tx < 128) { int b = tx >> 4, f = tx & 15;
        hTb0[b*HT_RS + 256 + f] = __float2half(xb[((b0 + b)*SS + 0)*FF + f]); }
    CLUSTER_SYNC();

    // ================= ENCODER =================
    for (int s = 0; s < SS; ++s) {
        const __half* hTc = (s & 1) ? hTb1 : hTb0;
        __half*       hTn = (s & 1) ? hTb0 : hTb1;
        unsigned int peerN = (s & 1) ? peerHT0 : peerHT1;

        float accA0[4] = {}, accA1[4] = {}, accB0[4] = {}, accB1[4] = {};
        unsigned int bb0, bb1;
        uint4 s1a[3], s2a[3];
        #pragma unroll
        for (int i2 = 0; i2 < 3; ++i2) {
            s1a[i2] = g_encWfrag[((13 + i2)*48 + mtg1)*32 + l];
            if (hv) s2a[i2] = g_encWfrag[((13 + i2)*48 + mtg2)*32 + l];
        }
        #pragma unroll
        for (int kt = 0; kt < 13; ++kt) {
            BFRAG(bb0, bb1, hTc, HT_RS, kt*16);
            uint4 a = wc[(kt*24 + m1)*32 + l];
            MMA(accA0, a, bb0, bb1);
            if (hv) { uint4 a2 = wc[(kt*24 + m2)*32 + l]; MMA(accA1, a2, bb0, bb1); }
        }
        #pragma unroll
        for (int i2 = 0; i2 < 3; ++i2) {
            BFRAG(bb0, bb1, hTc, HT_RS, (13 + i2)*16);
            MMA(accA0, s1a[i2], bb0, bb1);
            if (hv) MMA(accA1, s2a[i2], bb0, bb1);
        }
        {   // x tile (k 256..271 of h-table)
            BFRAG(bb0, bb1, hTc, HT_RS, 256);
            uint4 a = wc[(13*24 + m1)*32 + l];  MMA(accB0, a, bb0, bb1);
            if (hv) { uint4 a2 = wc[(13*24 + m2)*32 + l]; MMA(accB1, a2, bb0, bb1); }
        }
        {   // epilogue to gate planes (stride 10)
            int jr = (m1 & 7)*16 + (l >> 2), cb = (l & 3)*2;
            int g = m1 >> 3;
            *(float2*)&PL[(g*128 + jr)*10 + cb]     = make_float2(accA0[0]+accB0[0], accA0[1]+accB0[1]);
            *(float2*)&PL[(g*128 + jr + 8)*10 + cb] = make_float2(accA0[2]+accB0[2], accA0[3]+accB0[3]);
            if (hv) {
                int jr2 = (m2 & 7)*16 + (l >> 2);
                *(float2*)&PL[(256 + jr2)*10 + cb]     = make_float2(accA1[0], accA1[1]);
                *(float2*)&PL[(256 + jr2 + 8)*10 + cb] = make_float2(accA1[2], accA1[3]);
                *(float2*)&PL[(384 + jr2)*10 + cb]     = make_float2(accB1[0], accB1[1]);
                *(float2*)&PL[(384 + jr2 + 8)*10 + cb] = make_float2(accB1[2], accB1[3]);
            }
        }
        __syncthreads();
        {   // GRU update: own 128 j's; push h2 to both h-tables
            int jl = tx & 127, j = jbase + jl, pr = tx >> 7;
            #pragma unroll
            for (int q = 0; q < 2; ++q) {
                int b = pr*2 + q;
                float r = sigf(PL[jl*10 + b] + BI[jl]);
                float z = sigf(PL[(128 + jl)*10 + b] + BI[128 + jl]);
                float n = tanhf(PL[(384 + jl)*10 + b] + BI[256 + jl]
                              + r*(PL[(256 + jl)*10 + b] + BI[384 + jl]));
                float hold = hF[jl*10 + b];
                float h2 = (1.f - z)*n + z*hold;
                hF[jl*10 + b] = h2;
                __half hh = __float2half(h2);
                hTn[b*HT_RS + j] = hh;
                stc16(peerN + (unsigned)(b*HT_RS + j)*2, *(unsigned short*)&hh);
                g_eoutH[((size_t)(b0 + b)*SS + s)*HH + j] = hh;
            }
            if (tx < 128 && s + 1 < SS) { int b = tx >> 4, f = tx & 15;
                hTn[b*HT_RS + 256 + f] = __float2half(xb[((b0 + b)*SS + s + 1)*FF + f]); }
        }
        CLUSTER_SYNC();
    }

    // ================= DECODER setup =================
    for (int e = tx; e < WC_SLOTS*768; e += 512) {
        int slot = e / 768, m = (e % 768) >> 5, ll = e & 31;
        int mtg = (m >> 3)*16 + (int)rank*8 + (m & 7);
        wc[e] = g_decWfrag[(slot*48 + mtg)*32 + ll];
    }
    if (tx < 128) {
        BI[tx]       = dbih[jbase + tx]        + dbhh[jbase + tx];
        BI[128 + tx] = dbih[HH + jbase + tx]   + dbhh[HH + jbase + tx];
        BI[256 + tx] = dbih[2*HH + jbase + tx];
        BI[384 + tx] = dbhh[2*HH + jbase + tx];
    }
    for (int e = tx; e < SS; e += 512) AB[e] = attb[e];
    if (tx < 128) { int b = tx >> 4, f = tx & 15;
        hTb0[b*HT_RS + 256 + f] = __float2half(xb[((b0 + b)*SS + (SS - 1))*FF + f]); }
    __syncthreads();

    for (int p = 0; p < PP; ++p) {
        const __half* hTc = (p & 1) ? hTb1 : hTb0;
        __half*       hTn = (p & 1) ? hTb0 : hTb1;
        unsigned int peerN = (p & 1) ? peerHT0 : peerHT1;

        // ---- A: attention scores (both ranks compute all 336) ----
        {
            float ac0[4] = {}, ac1[4] = {};
            unsigned int bb0, bb1;
            bool two = (w < 5);
            uint4 p1 = g_attfrag[(0*21 + w)*32 + l], p2 = p1;
            if (two) p2 = g_attfrag[(0*21 + 16 + w)*32 + l];
            #pragma unroll 1
            for (int kt = 0; kt < 17; ++kt) {
                uint4 c1 = p1, c2 = p2;
                if (kt < 16) {
                    p1 = g_attfrag[((kt + 1)*21 + w)*32 + l];
                    if (two) p2 = g_attfrag[((kt + 1)*21 + 16 + w)*32 + l];
                }
                BFRAG(bb0, bb1, hTc, HT_RS, kt*16);
                MMA(ac0, c1, bb0, bb1);
                if (two) MMA(ac1, c2, bb0, bb1);
            }
            int cb = (l & 3)*2, ro = l >> 2;
            int sr = w*16 + ro;
            *(float2*)&PL[sr*8 + cb]       = make_float2(ac0[0] + AB[sr],     ac0[1] + AB[sr]);
            *(float2*)&PL[(sr + 8)*8 + cb] = make_float2(ac0[2] + AB[sr + 8], ac0[3] + AB[sr + 8]);
            if (two) {
                int sr2 = (16 + w)*16 + ro;
                *(float2*)&PL[sr2*8 + cb]       = make_float2(ac1[0] + AB[sr2],     ac1[1] + AB[sr2]);
                *(float2*)&PL[(sr2 + 8)*8 + cb] = make_float2(ac1[2] + AB[sr2 + 8], ac1[3] + AB[sr2 + 8]);
            }
        }
        __syncthreads();
        // ---- B: softmax (warp = batch row) ----
        if (w < 8) {
            float mx = -1e30f;
            for (int i = l; i < SS; i += 32) mx = fmaxf(mx, PL[i*8 + w]);
            #pragma unroll
            for (int o = 16; o; o >>= 1) mx = fmaxf(mx, __shfl_xor_sync(0xffffffffu, mx, o));
            float sum = 0.f;
            for (int i = l; i < SS; i += 32) {
                float e = __expf(PL[i*8 + w] - mx);
                PL[i*8 + w] = e; sum += e;
            }
            #pragma unroll
            for (int o = 16; o; o >>= 1) sum += __shfl_xor_sync(0xffffffffu, sum, o);
            float inv = 1.f / sum;
            for (int i = l; i < SS; i += 32) PL[i*8 + w] *= inv;
        }
        __syncthreads();
        // ---- C: combine own 128 h-cols; write cT to both ranks ----
        {
            int b = tx >> 6, t = tx & 63, shalf = t >> 5, cq = t & 31;
            const uint2* ep = (const uint2*)(g_eoutH + (size_t)(b0 + b)*SS*HH) + (int)rank*32 + cq;
            float c0 = 0, c1 = 0, c2 = 0, c3 = 0;
            int s0 = shalf*168;
            #pragma unroll 4
            for (int s2 = s0; s2 < s0 + 168; ++s2) {
                float a = PL[s2*8 + b];
                uint2 u = ep[(size_t)s2*64];
                float2 f01 = __half22float2(*(__half2*)&u.x);
                float2 f23 = __half22float2(*(__half2*)&u.y);
                c0 += a*f01.x; c1 += a*f01.y; c2 += a*f23.x; c3 += a*f23.y;
            }
            if (shalf) *(float4*)&SCR[(b*32 + cq)*4] = make_float4(c0, c1, c2, c3);
            __syncthreads();
            if (!shalf) {
                float4 pv = *(float4*)&SCR[(b*32 + cq)*4];
                c0 += pv.x; c1 += pv.y; c2 += pv.z; c3 += pv.w;
                __half2 lo = __floats2half2_rn(c0, c1), hi = __floats2half2_rn(c2, c3);
                int col = jbase + cq*4;
                *(__half2*)&cT[b*CT_RS + col]     = lo;
                *(__half2*)&cT[b*CT_RS + col + 2] = hi;
                unsigned int ad = peerCT + (unsigned)(b*CT_RS + col)*2;
                stc32(ad,     *(unsigned int*)&lo);
                stc32(ad + 4, *(unsigned int*)&hi);
            }
        }
        CLUSTER_SYNC();
        // ---- D: decoder GRU mma (kt<16: Whh x h; kt>=16: Wih x comb) ----
        {
            float accA0[4] = {}, accA1[4] = {}, accB0[4] = {}, accB1[4] = {};
            unsigned int bb0, bb1;
            #pragma unroll
            for (int kt = 0; kt < 14; ++kt) {
                BFRAG(bb0, bb1, hTc, HT_RS, kt*16);
                uint4 a = wc[(kt*24 + m1)*32 + l];
                MMA(accA0, a, bb0, bb1);
                if (hv) { uint4 a2 = wc[(kt*24 + m2)*32 + l]; MMA(accA1, a2, bb0, bb1); }
            }
            uint4 p1 = g_decWfrag[(14*48 + mtg1)*32 + l], p2 = p1;
            if (hv) p2 = g_decWfrag[(14*48 + mtg2)*32 + l];
            #pragma unroll 1
            for (int kt = 14; kt < 32; ++kt) {
                uint4 c1 = p1, c2 = p2;
                if (kt < 31) {
                    p1 = g_decWfrag[((kt + 1)*48 + mtg1)*32 + l];
                    if (hv) p2 = g_decWfrag[((kt + 1)*48 + mtg2)*32 + l];
                }
                if (kt < 16) {
                    BFRAG(bb0, bb1, hTc, HT_RS, kt*16);
                    MMA(accA0, c1, bb0, bb1);
                    if (hv) MMA(accA1, c2, bb0, bb1);
                } else {
                    BFRAG(bb0, bb1, cT, CT_RS, (kt - 16)*16);
                    MMA(accB0, c1, bb0, bb1);
                    if (hv) MMA(accB1, c2, bb0, bb1);
                }
            }
            int jr = (m1 & 7)*16 + (l >> 2), cb = (l & 3)*2;
            int g = m1 >> 3;
            *(float2*)&PL[(g*128 + jr)*10 + cb]     = make_float2(accA0[0]+accB0[0], accA0[1]+accB0[1]);
            *(float2*)&PL[(g*128 + jr + 8)*10 + cb] = make_float2(accA0[2]+accB0[2], accA0[3]+accB0[3]);
            if (hv) {
                int jr2 = (m2 & 7)*16 + (l >> 2);
                *(float2*)&PL[(256 + jr2)*10 + cb]     = make_float2(accA1[0], accA1[1]);
                *(float2*)&PL[(256 + jr2 + 8)*10 + cb] = make_float2(accA1[2], accA1[3]);
                *(float2*)&PL[(384 + jr2)*10 + cb]     = make_float2(accB1[0], accB1[1]);
                *(float2*)&PL[(384 + jr2 + 8)*10 + cb] = make_float2(accB1[2], accB1[3]);
            }
        }
        __syncthreads();
        {   // GRU update own j's; push h2 to both h-tables
            int jl = tx & 127, j = jbase + jl, pr = tx >> 7;
            #pragma unroll
            for (int q = 0; q < 2; ++q) {
                int b = pr*2 + q;
                float r = sigf(PL[jl*10 + b] + BI[jl]);
                float z = sigf(PL[(128 + jl)*10 + b] + BI[128 + jl]);
                float n = tanhf(PL[(384 + jl)*10 + b] + BI[256 + jl]
                              + r*(PL[(256 + jl)*10 + b] + BI[384 + jl]));
                float hold = hF[jl*10 + b];
                float h2 = (1.f - z)*n + z*hold;
                hF[jl*10 + b] = h2;
                __half hh = __float2half(h2);
                hTn[b*HT_RS + j] = hh;
                stc16(peerN + (unsigned)(b*HT_RS + j)*2, *(unsigned short*)&hh);
            }
        }
        CLUSTER_SYNC();
        // ---- E: out projection + final linear (both ranks; rank0 writes dout) ----
        if (w < 8) {
            float fin = 0.f;
            #pragma unroll
            for (int f = 0; f < FF; ++f) {
                float acc = 0.f;
                #pragma unroll
                for (int k = l; k < HH; k += 32)
                    acc += __half2float(hTn[w*HT_RS + k]) * outW[f*HH + k];
                #pragma unroll
                for (int o = 16; o; o >>= 1) acc += __shfl_xor_sync(0xffffffffu, acc, o);
                if (l == 0) {
                    float ov = acc + outb[f];
                    hTn[w*HT_RS + 256 + f] = __float2half(ov);
                    fin += ov * linW[f];
                }
            }
            if (l == 0 && rank == 0) dout[(b0 + w)*PP + p] = fin + linb[0];
        }
        __syncthreads();
    }
}

// ---------------- launch ----------------
extern "C" void kernel_launch(void* const* d_in, const int* in_sizes, int n_in,
                              void* d_out, int out_size)
{
    const float* xb   = (const float*)d_in[0];
    const float* eWih = (const float*)d_in[1];
    const float* eWhh = (const float*)d_in[2];
    const float* ebih = (const float*)d_in[3];
    const float* ebhh = (const float*)d_in[4];
    const float* attW = (const float*)d_in[5];
    const float* attb = (const float*)d_in[6];
    const float* dWih = (const float*)d_in[7];
    const float* dWhh = (const float*)d_in[8];
    const float* dbih = (const float*)d_in[9];
    const float* dbhh = (const float*)d_in[10];
    const float* outW = (const float*)d_in[11];
    const float* outb = (const float*)d_in[12];
    const float* linW = (const float*)d_in[13];
    const float* linb = (const float*)d_in[14];
    float* dout = (float*)d_out;

    cudaFuncSetAttribute(k_all, cudaFuncAttributeMaxDynamicSharedMemorySize, SMEM_BYTES);

    k_prep<<<(PREP_N + 255) / 256, 256>>>(eWih, eWhh, dWih, dWhh, attW);
    k_all<<<BB / 4, 512, SMEM_BYTES>>>(xb, ebih, ebhh, attb, dbih, dbhh,
                                       outW, outb, linW, linb, dout);
}